// round 11
// baseline (speedup 1.0000x reference)
#include <cuda_runtime.h>
#include <cuda_bf16.h>
#include <math.h>
#include <stdint.h>

#define DIMC 1024
#define NH 16
#define HD 64
#define BATCH 4
#define SEQ 2048
#define BT (BATCH*SEQ)
#define MK ((size_t)BT*DIMC)
#define BHD ((size_t)BATCH*NH*SEQ*HD)

// ---------------- scratch (allocation-free) ----------------
__device__ float g_v[BHD];
__device__ __nv_bfloat16 g_qhi[BHD], g_qlo[BHD];
__device__ __nv_bfloat16 g_khi[BHD], g_klo[BHD];
__device__ __nv_bfloat16 g_vthi[BHD], g_vtlo[BHD];
__device__ __nv_bfloat16 g_ahi[3*MK];
__device__ __nv_bfloat16 g_alo[3*MK];
__device__ __nv_bfloat16 g_whi[4*(size_t)DIMC*DIMC];
__device__ __nv_bfloat16 g_wlo[4*(size_t)DIMC*DIMC];
__device__ float2 g_rope[SEQ*32];

// ---------------- PTX helpers ----------------
__device__ __forceinline__ uint32_t smem_u32(const void* p) {
    uint32_t a;
    asm("{ .reg .u64 t; cvta.to.shared.u64 t, %1; cvt.u32.u64 %0, t; }" : "=r"(a) : "l"(p));
    return a;
}
__device__ __forceinline__ void cpasync16(uint32_t saddr, const void* g) {
    asm volatile("cp.async.cg.shared.global [%0], [%1], 16;" :: "r"(saddr), "l"(g));
}
__device__ __forceinline__ void ldsm4(uint32_t* r, uint32_t addr) {
    asm volatile("ldmatrix.sync.aligned.m8n8.x4.shared.b16 {%0,%1,%2,%3}, [%4];"
                 : "=r"(r[0]), "=r"(r[1]), "=r"(r[2]), "=r"(r[3]) : "r"(addr));
}
__device__ __forceinline__ void mma16816(float* d, const uint32_t* a, uint32_t b0, uint32_t b1) {
    asm volatile("mma.sync.aligned.m16n8k16.row.col.f32.bf16.bf16.f32 "
                 "{%0,%1,%2,%3}, {%4,%5,%6,%7}, {%8,%9}, {%0,%1,%2,%3};"
                 : "+f"(d[0]), "+f"(d[1]), "+f"(d[2]), "+f"(d[3])
                 : "r"(a[0]), "r"(a[1]), "r"(a[2]), "r"(a[3]), "r"(b0), "r"(b1));
}
__device__ __forceinline__ uint32_t packbf(float a, float b) {
    __nv_bfloat162 t = __floats2bfloat162_rn(a, b);
    return *(uint32_t*)&t;
}
__device__ __forceinline__ float flo(float x) {
    return x - __bfloat162float(__float2bfloat16(x));
}
__device__ __forceinline__ float fexp2(float t) {
    t = fmaxf(t, -30.0f);
    float r = t + 12582912.0f;
    int n = __float_as_int(r) - 0x4B400000;
    float f = t - (r - 12582912.0f);
    float p = 1.3333558146e-3f;
    p = fmaf(p, f, 9.6181291077e-3f);
    p = fmaf(p, f, 5.5504108664e-2f);
    p = fmaf(p, f, 2.4022650696e-1f);
    p = fmaf(p, f, 6.9314718056e-1f);
    p = fmaf(p, f, 1.0f);
    return __int_as_float(__float_as_int(p) + (n << 23));
}

// ---------------- helper kernels ----------------
__global__ __launch_bounds__(256) void rope_table_kernel() {
    int idx = blockIdx.x * 256 + threadIdx.x;
    int t = idx >> 5, f = idx & 31;
    double invf = 1.0 / pow(10000.0, (double)(2 * f) / 64.0);
    float ang = (float)t * (float)invf;
    g_rope[idx] = make_float2((float)cos((double)ang), (float)sin((double)ang));
}

__global__ __launch_bounds__(256) void asplit3_kernel(const float4* __restrict__ q,
                                                      const float4* __restrict__ k,
                                                      const float4* __restrict__ v) {
    int z = blockIdx.y;
    const float4* src = (z == 0) ? q : (z == 1) ? k : v;
    size_t i = blockIdx.x * 256 + threadIdx.x;
    float4 val = src[i];
    float vv[4] = {val.x, val.y, val.z, val.w};
    __nv_bfloat16 h[4], l[4];
    #pragma unroll
    for (int j = 0; j < 4; j++) {
        h[j] = __float2bfloat16(vv[j]);
        l[j] = __float2bfloat16(vv[j] - __bfloat162float(h[j]));
    }
    size_t o = z * MK + 4 * i;
    *(uint2*)(g_ahi + o) = *(uint2*)h;
    *(uint2*)(g_alo + o) = *(uint2*)l;
}

__global__ __launch_bounds__(256) void wsplit4_kernel(const float* __restrict__ Wq,
                                                      const float* __restrict__ Wk,
                                                      const float* __restrict__ Wv,
                                                      const float* __restrict__ Wo) {
    __shared__ float tile[32][33];
    int z = blockIdx.z;
    const float* W = (z == 0) ? Wq : (z == 1) ? Wk : (z == 2) ? Wv : Wo;
    size_t wof = (size_t)z * DIMC * DIMC;
    int n0 = blockIdx.x * 32, k0 = blockIdx.y * 32;
    int x = threadIdx.x, y0 = threadIdx.y;
    for (int j = y0; j < 32; j += 8)
        tile[j][x] = W[(size_t)(k0 + j) * DIMC + n0 + x];
    __syncthreads();
    for (int j = y0; j < 32; j += 8) {
        float v = tile[x][j];
        __nv_bfloat16 h = __float2bfloat16(v);
        size_t o = wof + (size_t)(n0 + j) * DIMC + k0 + x;
        g_whi[o] = h;
        g_wlo[o] = __float2bfloat16(v - __bfloat162float(h));
    }
}

__global__ __launch_bounds__(256) void vtrans_kernel() {
    __shared__ float tile[64][65];
    int s0 = blockIdx.x * 64;
    int bh = blockIdx.y;
    const float* Vb = g_v + (size_t)bh * SEQ * HD;
    int tid = threadIdx.x;
    #pragma unroll
    for (int j = 0; j < 4; j++) {
        int idx = tid + j * 256;
        int r = idx >> 4, c4 = (idx & 15) << 2;
        float4 v = *(const float4*)(Vb + (size_t)(s0 + r) * HD + c4);
        tile[c4 + 0][r] = v.x; tile[c4 + 1][r] = v.y;
        tile[c4 + 2][r] = v.z; tile[c4 + 3][r] = v.w;
    }
    __syncthreads();
    size_t ob = (size_t)bh * HD * SEQ + s0;
    #pragma unroll
    for (int j = 0; j < 8; j++) {
        int u = tid + j * 256;
        int d = u >> 5, sp = u & 31;
        float e = tile[d][2 * sp], o = tile[d][2 * sp + 1];
        *(uint32_t*)(g_vthi + ob + (size_t)d * SEQ + 2 * sp) = packbf(e, o);
        *(uint32_t*)(g_vtlo + ob + (size_t)d * SEQ + 2 * sp) = packbf(flo(e), flo(o));
    }
}

// ---------------- 3-stage cp.async HMMA GEMM, XOR-swizzled 64B rows ----------------
// Row = 64 B (32 bf16), chunk c (16B) of row r stored at (c ^ ((r>>1)&3)).
// LDSM phases conflict-free; every address 16B-aligned. One barrier per K-iter.
#define ROW_B 64
#define ARR_B (128*ROW_B)            // 8192 B
#define STAGE_B (4*ARR_B)            // 32768 B
#define GSMEM_BYTES (3*STAGE_B)      // 98304 B (2 CTAs/SM: 196608 <= 228K)

template<int MODE>
__global__ __launch_bounds__(256, 2) void pgemm_kernel(const float* __restrict__ b0p,
                                                       const float* __restrict__ b1p,
                                                       const float* __restrict__ b2p,
                                                       float* __restrict__ outp)
{
    extern __shared__ uint32_t smu[];
    const uint32_t su = smem_u32(smu);

    const int tid  = threadIdx.x;
    const int lane = tid & 31;
    const int wid  = tid >> 5;
    const int wm = wid & 1;
    const int wn = wid >> 1;
    const int m0 = blockIdx.y << 7, n0 = blockIdx.x << 7;
    const int z = (MODE == 0) ? blockIdx.z : 3;

    const __nv_bfloat16* ahi = g_ahi + ((MODE == 0) ? (size_t)z * MK : 0) + (size_t)m0 * DIMC;
    const __nv_bfloat16* alo = g_alo + ((MODE == 0) ? (size_t)z * MK : 0) + (size_t)m0 * DIMC;
    const __nv_bfloat16* whi = g_whi + (size_t)z * DIMC * DIMC + (size_t)n0 * DIMC;
    const __nv_bfloat16* wlo = g_wlo + (size_t)z * DIMC * DIMC + (size_t)n0 * DIMC;
    const float* bias = (MODE == 1) ? b0p : (z == 0) ? b0p : (z == 1) ? b1p : b2p;

    float acc[4][4][4];
    #pragma unroll
    for (int i = 0; i < 4; i++)
        #pragma unroll
        for (int j = 0; j < 4; j++)
            #pragma unroll
            for (int r = 0; r < 4; r++) acc[i][j][r] = 0.f;

    // ldmatrix per-lane offsets (bytes, within one 16-row tile, per ks2)
    const int a_row = (lane & 7) + 8 * ((lane >> 3) & 1);
    const int a_cs  = (lane >> 4) & 1;
    const int b_row = (lane & 7) + 8 * ((lane >> 4) & 1);
    const int b_cs  = (lane >> 3) & 1;
    const int a_sw = (a_row >> 1) & 3, b_sw = (b_row >> 1) & 3;
    uint32_t a_off[2], b_off[2];
    #pragma unroll
    for (int ks2 = 0; ks2 < 2; ks2++) {
        a_off[ks2] = (uint32_t)(a_row * ROW_B + (((ks2 << 1) | a_cs) ^ a_sw) * 16);
        b_off[ks2] = (uint32_t)(b_row * ROW_B + (((ks2 << 1) | b_cs) ^ b_sw) * 16);
    }

    // cp.async geometry: 512 16B-chunks per array, 2 per thread
    const int l_row = tid >> 1;                 // 0..127
    const int l_cb  = (tid & 1) << 1;           // chunk base 0 or 2
    const int l_sw  = (l_row >> 1) & 3;

    auto issue = [&](int c, int buf) {
        int k0 = c << 5;
        uint32_t base = su + (uint32_t)buf * STAGE_B;
        #pragma unroll
        for (int j = 0; j < 2; j++) {
            int ch = l_cb + j;                  // source chunk 0..3
            size_t g = (size_t)l_row * DIMC + k0 + ch * 8;
            uint32_t so = (uint32_t)(l_row * ROW_B + (ch ^ l_sw) * 16);
            cpasync16(base + 0 * ARR_B + so, ahi + g);
            cpasync16(base + 1 * ARR_B + so, alo + g);
            cpasync16(base + 2 * ARR_B + so, whi + g);
            cpasync16(base + 3 * ARR_B + so, wlo + g);
        }
        asm volatile("cp.async.commit_group;");
    };

    issue(0, 0);
    issue(1, 1);
    for (int c = 0; c < 32; c++) {
        if (c < 31) { asm volatile("cp.async.wait_group 1;"); }
        else        { asm volatile("cp.async.wait_group 0;"); }
        __syncthreads();
        if (c + 2 < 32) issue(c + 2, (c + 2) % 3);

        uint32_t sb = su + (uint32_t)(c % 3) * STAGE_B;

        #pragma unroll
        for (int ks2 = 0; ks2 < 2; ks2++) {
            uint32_t ah[4][4], al[4][4], bh[2][4], bl[2][4];
            #pragma unroll
            for (int mt = 0; mt < 4; mt++) {
                uint32_t ab = sb + (uint32_t)((wm * 64 + mt * 16) * ROW_B) + a_off[ks2];
                ldsm4(ah[mt], ab);
                ldsm4(al[mt], ab + ARR_B);
            }
            #pragma unroll
            for (int p = 0; p < 2; p++) {
                uint32_t bb = sb + 2 * ARR_B + (uint32_t)((wn * 32 + p * 16) * ROW_B) + b_off[ks2];
                ldsm4(bh[p], bb);
                ldsm4(bl[p], bb + ARR_B);
            }
            #pragma unroll
            for (int mt = 0; mt < 4; mt++)
                #pragma unroll
                for (int nt = 0; nt < 4; nt++) {
                    int p = nt >> 1, ix = (nt & 1) * 2;
                    mma16816(acc[mt][nt], ah[mt], bh[p][ix], bh[p][ix + 1]);
                    mma16816(acc[mt][nt], ah[mt], bl[p][ix], bl[p][ix + 1]);
                    mma16816(acc[mt][nt], al[mt], bh[p][ix], bh[p][ix + 1]);
                }
        }
    }

    const int quad = lane >> 2, tc = lane & 3;
    #pragma unroll
    for (int mt = 0; mt < 4; mt++) {
        #pragma unroll
        for (int nt = 0; nt < 4; nt++) {
            #pragma unroll
            for (int half = 0; half < 2; half++) {
                int m = m0 + wm * 64 + mt * 16 + quad + half * 8;
                int n = n0 + wn * 32 + nt * 8 + tc * 2;
                float v0 = acc[mt][nt][half * 2]     + bias[n];
                float v1 = acc[mt][nt][half * 2 + 1] + bias[n + 1];
                if (MODE == 0) {
                    int b = m >> 11, t = m & (SEQ - 1);
                    int h = n >> 6, d = n & 63;
                    size_t base = ((size_t)(b * NH + h) * SEQ + t) * HD + d;
                    if (z == 2) {
                        g_v[base]     = v0;
                        g_v[base + 1] = v1;
                    } else {
                        float2 cs = g_rope[t * 32 + (d >> 1)];
                        float oe = v0 * cs.x - v1 * cs.y;
                        float oo = v0 * cs.y + v1 * cs.x;
                        uint32_t hi = packbf(oe, oo);
                        uint32_t lo = packbf(flo(oe), flo(oo));
                        if (z == 0) {
                            *(uint32_t*)(g_qhi + base) = hi;
                            *(uint32_t*)(g_qlo + base) = lo;
                        } else {
                            *(uint32_t*)(g_khi + base) = hi;
                            *(uint32_t*)(g_klo + base) = lo;
                        }
                    }
                } else {
                    size_t base = (size_t)m * DIMC + n;
                    outp[base]     = v0;
                    outp[base + 1] = v1;
                }
            }
        }
    }
}

// ---------------- attention: 3-stage cp.async, one barrier per tile ----------------
// Rows 144B (16B-aligned) — layout unchanged from proven R9 geometry.
#define ASV 36
#define AARR (64*ASV)
#define ASTG (4*AARR)
#define ATT_SMEM_BYTES (3*ASTG*4)   // 110592

__global__ __launch_bounds__(256, 2) void attn_kernel()
{
    extern __shared__ uint32_t smu[];
    const uint32_t su = smem_u32(smu);

    const int tid  = threadIdx.x;
    const int lane = tid & 31;
    const int wid  = tid >> 5;
    const int bh   = blockIdx.y;
    const int m0   = ((int)gridDim.x - 1 - (int)blockIdx.x) * 128;

    const size_t bhb = (size_t)bh * SEQ * HD;
    const __nv_bfloat16* Khi = g_khi + bhb;
    const __nv_bfloat16* Klo = g_klo + bhb;
    const __nv_bfloat16* Vthi = g_vthi + bhb;
    const __nv_bfloat16* Vtlo = g_vtlo + bhb;

    const uint32_t a_loff = (uint32_t)(((lane & 7) + 8 * ((lane >> 3) & 1)) * ASV * 4
                                       + ((lane >> 4) & 1) * 16);
    const uint32_t b_loff = (uint32_t)(((lane & 7) + 8 * ((lane >> 4) & 1)) * ASV * 4
                                       + ((lane >> 3) & 1) * 16);

    {
        const __nv_bfloat16* Qhi = g_qhi + bhb + (size_t)m0 * HD;
        const __nv_bfloat16* Qlo = g_qlo + bhb + (size_t)m0 * HD;
        #pragma unroll
        for (int j = 0; j < 4; j++) {
            int idx = tid + j * 256;
            int row = idx >> 3, seg = idx & 7;
            size_t g = (size_t)row * HD + seg * 8;
            int o = row * ASV + seg * 4;
            *(uint4*)(smu + o)        = *(const uint4*)(Qhi + g);
            *(uint4*)(smu + 4608 + o) = *(const uint4*)(Qlo + g);
        }
    }
    __syncthreads();
    uint32_t qh[4][4], ql[4][4];
    #pragma unroll
    for (int ks = 0; ks < 4; ks++) {
        uint32_t ab = su + (uint32_t)(wid * 16 * ASV * 4) + ks * 32 + a_loff;
        ldsm4(qh[ks], ab);
        ldsm4(ql[ks], ab + 4608 * 4);
    }
    __syncthreads();

    float oacc[8][4];
    #pragma unroll
    for (int nt = 0; nt < 8; nt++)
        #pragma unroll
        for (int e = 0; e < 4; e++) oacc[nt][e] = 0.f;
    float mr[2] = {-1e30f, -1e30f};
    float lr[2] = {0.f, 0.f};

    const int qr = lane >> 2, qc = lane & 3;
    const int rowbase = m0 + wid * 16;
    const int ntiles = m0 / 64 + 2;

    const int l_row = tid >> 2, l_seg = tid & 3;

    auto issue = [&](int tix, int buf) {
        int s0 = tix * 64;
        uint32_t base = su + (uint32_t)buf * ASTG * 4;
        #pragma unroll
        for (int ss = 0; ss < 2; ss++) {
            int seg = l_seg + ss * 4;
            uint32_t so = (uint32_t)(l_row * ASV + seg * 4) * 4;
            size_t gk = (size_t)(s0 + l_row) * HD + seg * 8;
            size_t gv = (size_t)l_row * SEQ + s0 + seg * 8;
            cpasync16(base + 0 * AARR * 4 + so, Khi + gk);
            cpasync16(base + 1 * AARR * 4 + so, Klo + gk);
            cpasync16(base + 2 * AARR * 4 + so, Vthi + gv);
            cpasync16(base + 3 * AARR * 4 + so, Vtlo + gv);
        }
        asm volatile("cp.async.commit_group;");
    };

    issue(0, 0);
    issue(1, 1);
    for (int tix = 0; tix < ntiles; tix++) {
        int s0 = tix * 64;
        if (tix + 1 < ntiles) { asm volatile("cp.async.wait_group 1;"); }
        else                  { asm volatile("cp.async.wait_group 0;"); }
        __syncthreads();
        if (tix + 2 < ntiles) issue(tix + 2, (tix + 2) % 3);

        if (s0 <= rowbase + 15) {
            uint32_t kvB = su + (uint32_t)(tix % 3) * ASTG * 4;

            float sacc[8][4];
            #pragma unroll
            for (int nt = 0; nt < 8; nt++)
                #pragma unroll
                for (int e = 0; e < 4; e++) sacc[nt][e] = 0.f;

            #pragma unroll
            for (int ks = 0; ks < 4; ks++) {
                #pragma unroll
                for (int p = 0; p < 4; p++) {
                    uint32_t bb = kvB + (uint32_t)(p * 16 * ASV * 4) + ks * 32 + b_loff;
                    uint32_t bhf[4], blf[4];
                    ldsm4(bhf, bb);
                    ldsm4(blf, bb + AARR * 4);
                    mma16816(sacc[2*p],   qh[ks], bhf[0], bhf[1]);
                    mma16816(sacc[2*p],   qh[ks], blf[0], blf[1]);
                    mma16816(sacc[2*p],   ql[ks], bhf[0], bhf[1]);
                    mma16816(sacc[2*p+1], qh[ks], bhf[2], bhf[3]);
                    mma16816(sacc[2*p+1], qh[ks], blf[2], blf[3]);
                    mma16816(sacc[2*p+1], ql[ks], bhf[2], bhf[3]);
                }
            }

            if (s0 + 63 > rowbase) {
                int rA = rowbase + qr, rB = rA + 8;
                #pragma unroll
                for (int nt = 0; nt < 8; nt++) {
                    int c0 = s0 + nt * 8 + qc * 2;
                    if (c0 > rA)     sacc[nt][0] = -1e30f;
                    if (c0 + 1 > rA) sacc[nt][1] = -1e30f;
                    if (c0 > rB)     sacc[nt][2] = -1e30f;
                    if (c0 + 1 > rB) sacc[nt][3] = -1e30f;
                }
            }

            float mxA = -1e30f, mxB = -1e30f;
            #pragma unroll
            for (int nt = 0; nt < 8; nt++) {
                mxA = fmaxf(mxA, fmaxf(sacc[nt][0], sacc[nt][1]));
                mxB = fmaxf(mxB, fmaxf(sacc[nt][2], sacc[nt][3]));
            }
            mxA = fmaxf(mxA, __shfl_xor_sync(0xffffffffu, mxA, 1));
            mxA = fmaxf(mxA, __shfl_xor_sync(0xffffffffu, mxA, 2));
            mxB = fmaxf(mxB, __shfl_xor_sync(0xffffffffu, mxB, 1));
            mxB = fmaxf(mxB, __shfl_xor_sync(0xffffffffu, mxB, 2));
            mxA *= 0.125f; mxB *= 0.125f;

            float mnA = fmaxf(mr[0], mxA), mnB = fmaxf(mr[1], mxB);
            float corrA = fexp2((mr[0] - mnA) * 1.44269504f);
            float corrB = fexp2((mr[1] - mnB) * 1.44269504f);
            mr[0] = mnA; mr[1] = mnB;
            float nbA = mnA * 1.44269504f, nbB = mnB * 1.44269504f;

            const float C1 = 0.125f * 1.44269504f;
            float suA = 0.f, suB = 0.f;
            #pragma unroll
            for (int nt = 0; nt < 8; nt++) {
                float p0 = fexp2(fmaf(sacc[nt][0], C1, -nbA));
                float p1 = fexp2(fmaf(sacc[nt][1], C1, -nbA));
                float p2 = fexp2(fmaf(sacc[nt][2], C1, -nbB));
                float p3 = fexp2(fmaf(sacc[nt][3], C1, -nbB));
                sacc[nt][0] = p0; sacc[nt][1] = p1;
                sacc[nt][2] = p2; sacc[nt][3] = p3;
                suA += p0 + p1; suB += p2 + p3;
            }
            suA += __shfl_xor_sync(0xffffffffu, suA, 1);
            suA += __shfl_xor_sync(0xffffffffu, suA, 2);
            suB += __shfl_xor_sync(0xffffffffu, suB, 1);
            suB += __shfl_xor_sync(0xffffffffu, suB, 2);
            lr[0] = lr[0] * corrA + suA;
            lr[1] = lr[1] * corrB + suB;
            #pragma unroll
            for (int nt = 0; nt < 8; nt++) {
                oacc[nt][0] *= corrA; oacc[nt][1] *= corrA;
                oacc[nt][2] *= corrB; oacc[nt][3] *= corrB;
            }

            uint32_t ph[4][4], pl[4][4];
            #pragma unroll
            for (int kk = 0; kk < 4; kk++) {
                float a0 = sacc[2*kk][0],   a1 = sacc[2*kk][1];
                float a2 = sacc[2*kk][2],   a3 = sacc[2*kk][3];
                float b0 = sacc[2*kk+1][0], b1 = sacc[2*kk+1][1];
                float b2 = sacc[2*kk+1][2], b3 = sacc[2*kk+1][3];
                ph[kk][0] = packbf(a0, a1); ph[kk][1] = packbf(a2, a3);
                ph[kk][2] = packbf(b0, b1); ph[kk][3] = packbf(b2, b3);
                pl[kk][0] = packbf(flo(a0), flo(a1)); pl[kk][1] = packbf(flo(a2), flo(a3));
                pl[kk][2] = packbf(flo(b0), flo(b1)); pl[kk][3] = packbf(flo(b2), flo(b3));
            }

            uint32_t vbB = kvB + 2 * AARR * 4;
            #pragma unroll
            for (int kk = 0; kk < 4; kk++) {
                #pragma unroll
                for (int p = 0; p < 4; p++) {
                    uint32_t vb = vbB + (uint32_t)(p * 16 * ASV * 4) + kk * 32 + b_loff;
                    uint32_t vhf[4], vlf[4];
                    ldsm4(vhf, vb);
                    ldsm4(vlf, vb + AARR * 4);
                    mma16816(oacc[2*p],   ph[kk], vhf[0], vhf[1]);
                    mma16816(oacc[2*p],   ph[kk], vlf[0], vlf[1]);
                    mma16816(oacc[2*p],   pl[kk], vhf[0], vhf[1]);
                    mma16816(oacc[2*p+1], ph[kk], vhf[2], vhf[3]);
                    mma16816(oacc[2*p+1], ph[kk], vlf[2], vlf[3]);
                    mma16816(oacc[2*p+1], pl[kk], vhf[2], vhf[3]);
                }
            }
        }
    }

    float ivA = 1.0f / lr[0], ivB = 1.0f / lr[1];
    int b = bh >> 4, h = bh & 15;
    int rA = rowbase + qr, rB = rA + 8;
    #pragma unroll
    for (int nt = 0; nt < 8; nt++) {
        int d = nt * 8 + qc * 2;
        size_t iA = ((size_t)(b * SEQ + rA)) * DIMC + h * HD + d;
        size_t iB = ((size_t)(b * SEQ + rB)) * DIMC + h * HD + d;
        float o0 = oacc[nt][0] * ivA, o1 = oacc[nt][1] * ivA;
        float o2 = oacc[nt][2] * ivB, o3 = oacc[nt][3] * ivB;
        *(uint32_t*)(g_ahi + iA) = packbf(o0, o1);
        *(uint32_t*)(g_alo + iA) = packbf(flo(o0), flo(o1));
        *(uint32_t*)(g_ahi + iB) = packbf(o2, o3);
        *(uint32_t*)(g_alo + iB) = packbf(flo(o2), flo(o3));
    }
}

// ---------------- launch ----------------
extern "C" void kernel_launch(void* const* d_in, const int* in_sizes, int n_in,
                              void* d_out, int out_size)
{
    const float* query = (const float*)d_in[0];
    const float* key   = (const float*)d_in[1];
    const float* value = (const float*)d_in[2];
    const float* Wq = (const float*)d_in[3];
    const float* bq = (const float*)d_in[4];
    const float* Wk = (const float*)d_in[5];
    const float* bk = (const float*)d_in[6];
    const float* Wv = (const float*)d_in[7];
    const float* bv = (const float*)d_in[8];
    const float* Wo = (const float*)d_in[9];
    const float* bo = (const float*)d_in[10];
    float* out = (float*)d_out;

    cudaFuncSetAttribute(pgemm_kernel<0>, cudaFuncAttributeMaxDynamicSharedMemorySize, GSMEM_BYTES);
    cudaFuncSetAttribute(pgemm_kernel<1>, cudaFuncAttributeMaxDynamicSharedMemorySize, GSMEM_BYTES);
    cudaFuncSetAttribute(attn_kernel, cudaFuncAttributeMaxDynamicSharedMemorySize, ATT_SMEM_BYTES);

    int n4 = BT * DIMC / 4;

    rope_table_kernel<<<SEQ * 32 / 256, 256>>>();
    asplit3_kernel<<<dim3(n4 / 256, 3), 256>>>((const float4*)query,
                                               (const float4*)key,
                                               (const float4*)value);
    wsplit4_kernel<<<dim3(32, 32, 4), dim3(32, 8)>>>(Wq, Wk, Wv, Wo);

    pgemm_kernel<0><<<dim3(8, 64, 3), 256, GSMEM_BYTES>>>(bq, bk, bv, nullptr);

    vtrans_kernel<<<dim3(SEQ / 64, BATCH * NH), 256>>>();

    attn_kernel<<<dim3(SEQ / 128, BATCH * NH), 256, ATT_SMEM_BYTES>>>();

    pgemm_kernel<1><<<dim3(8, 64, 1), 256, GSMEM_BYTES>>>(bo, nullptr, nullptr, out);
}

// round 12
// speedup vs baseline: 1.0110x; 1.0110x over previous
#include <cuda_runtime.h>
#include <cuda_bf16.h>
#include <math.h>
#include <stdint.h>

#define DIMC 1024
#define NH 16
#define HD 64
#define BATCH 4
#define SEQ 2048
#define BT (BATCH*SEQ)
#define MK ((size_t)BT*DIMC)
#define BHD ((size_t)BATCH*NH*SEQ*HD)

// ---------------- scratch (allocation-free) ----------------
__device__ float g_v[BHD];
__device__ __nv_bfloat16 g_qhi[BHD], g_qlo[BHD];
__device__ __nv_bfloat16 g_khi[BHD], g_klo[BHD];
__device__ __nv_bfloat16 g_vthi[BHD], g_vtlo[BHD];
__device__ __nv_bfloat16 g_ahi[3*MK];
__device__ __nv_bfloat16 g_alo[3*MK];
__device__ __nv_bfloat16 g_whi[4*(size_t)DIMC*DIMC];
__device__ __nv_bfloat16 g_wlo[4*(size_t)DIMC*DIMC];
__device__ float2 g_rope[SEQ*32];

// ---------------- PTX helpers ----------------
__device__ __forceinline__ uint32_t smem_u32(const void* p) {
    uint32_t a;
    asm("{ .reg .u64 t; cvta.to.shared.u64 t, %1; cvt.u32.u64 %0, t; }" : "=r"(a) : "l"(p));
    return a;
}
__device__ __forceinline__ void cpasync16(uint32_t saddr, const void* g) {
    asm volatile("cp.async.cg.shared.global [%0], [%1], 16;" :: "r"(saddr), "l"(g));
}
__device__ __forceinline__ void ldsm4(uint32_t* r, uint32_t addr) {
    asm volatile("ldmatrix.sync.aligned.m8n8.x4.shared.b16 {%0,%1,%2,%3}, [%4];"
                 : "=r"(r[0]), "=r"(r[1]), "=r"(r[2]), "=r"(r[3]) : "r"(addr));
}
__device__ __forceinline__ void mma16816(float* d, const uint32_t* a, uint32_t b0, uint32_t b1) {
    asm volatile("mma.sync.aligned.m16n8k16.row.col.f32.bf16.bf16.f32 "
                 "{%0,%1,%2,%3}, {%4,%5,%6,%7}, {%8,%9}, {%0,%1,%2,%3};"
                 : "+f"(d[0]), "+f"(d[1]), "+f"(d[2]), "+f"(d[3])
                 : "r"(a[0]), "r"(a[1]), "r"(a[2]), "r"(a[3]), "r"(b0), "r"(b1));
}
__device__ __forceinline__ uint32_t packbf(float a, float b) {
    __nv_bfloat162 t = __floats2bfloat162_rn(a, b);
    return *(uint32_t*)&t;
}
__device__ __forceinline__ float flo(float x) {
    return x - __bfloat162float(__float2bfloat16(x));
}
__device__ __forceinline__ float fexp2(float t) {
    t = fmaxf(t, -30.0f);
    float r = t + 12582912.0f;
    int n = __float_as_int(r) - 0x4B400000;
    float f = t - (r - 12582912.0f);
    float p = 1.3333558146e-3f;
    p = fmaf(p, f, 9.6181291077e-3f);
    p = fmaf(p, f, 5.5504108664e-2f);
    p = fmaf(p, f, 2.4022650696e-1f);
    p = fmaf(p, f, 6.9314718056e-1f);
    p = fmaf(p, f, 1.0f);
    return __int_as_float(__float_as_int(p) + (n << 23));
}

// ---------------- helper kernels ----------------
__global__ __launch_bounds__(256) void rope_table_kernel() {
    int idx = blockIdx.x * 256 + threadIdx.x;
    int t = idx >> 5, f = idx & 31;
    double invf = 1.0 / pow(10000.0, (double)(2 * f) / 64.0);
    float ang = (float)t * (float)invf;
    g_rope[idx] = make_float2((float)cos((double)ang), (float)sin((double)ang));
}

__global__ __launch_bounds__(256) void asplit3_kernel(const float4* __restrict__ q,
                                                      const float4* __restrict__ k,
                                                      const float4* __restrict__ v) {
    int z = blockIdx.y;
    const float4* src = (z == 0) ? q : (z == 1) ? k : v;
    size_t i = blockIdx.x * 256 + threadIdx.x;
    float4 val = src[i];
    float vv[4] = {val.x, val.y, val.z, val.w};
    __nv_bfloat16 h[4], l[4];
    #pragma unroll
    for (int j = 0; j < 4; j++) {
        h[j] = __float2bfloat16(vv[j]);
        l[j] = __float2bfloat16(vv[j] - __bfloat162float(h[j]));
    }
    size_t o = z * MK + 4 * i;
    *(uint2*)(g_ahi + o) = *(uint2*)h;
    *(uint2*)(g_alo + o) = *(uint2*)l;
}

__global__ __launch_bounds__(256) void wsplit4_kernel(const float* __restrict__ Wq,
                                                      const float* __restrict__ Wk,
                                                      const float* __restrict__ Wv,
                                                      const float* __restrict__ Wo) {
    __shared__ float tile[32][33];
    int z = blockIdx.z;
    const float* W = (z == 0) ? Wq : (z == 1) ? Wk : (z == 2) ? Wv : Wo;
    size_t wof = (size_t)z * DIMC * DIMC;
    int n0 = blockIdx.x * 32, k0 = blockIdx.y * 32;
    int x = threadIdx.x, y0 = threadIdx.y;
    for (int j = y0; j < 32; j += 8)
        tile[j][x] = W[(size_t)(k0 + j) * DIMC + n0 + x];
    __syncthreads();
    for (int j = y0; j < 32; j += 8) {
        float v = tile[x][j];
        __nv_bfloat16 h = __float2bfloat16(v);
        size_t o = wof + (size_t)(n0 + j) * DIMC + k0 + x;
        g_whi[o] = h;
        g_wlo[o] = __float2bfloat16(v - __bfloat162float(h));
    }
}

__global__ __launch_bounds__(256) void vtrans_kernel() {
    __shared__ float tile[64][65];
    int s0 = blockIdx.x * 64;
    int bh = blockIdx.y;
    const float* Vb = g_v + (size_t)bh * SEQ * HD;
    int tid = threadIdx.x;
    #pragma unroll
    for (int j = 0; j < 4; j++) {
        int idx = tid + j * 256;
        int r = idx >> 4, c4 = (idx & 15) << 2;
        float4 v = *(const float4*)(Vb + (size_t)(s0 + r) * HD + c4);
        tile[c4 + 0][r] = v.x; tile[c4 + 1][r] = v.y;
        tile[c4 + 2][r] = v.z; tile[c4 + 3][r] = v.w;
    }
    __syncthreads();
    size_t ob = (size_t)bh * HD * SEQ + s0;
    #pragma unroll
    for (int j = 0; j < 8; j++) {
        int u = tid + j * 256;
        int d = u >> 5, sp = u & 31;
        float e = tile[d][2 * sp], o = tile[d][2 * sp + 1];
        *(uint32_t*)(g_vthi + ob + (size_t)d * SEQ + 2 * sp) = packbf(e, o);
        *(uint32_t*)(g_vtlo + ob + (size_t)d * SEQ + 2 * sp) = packbf(flo(e), flo(o));
    }
}

// ---------------- 3-stage cp.async HMMA GEMM, XOR-swizzled 64B rows ----------------
// MMA issue = three passes over all 16 tiles (hh, hl, lh): RAW distance 16.
// Per-accumulator order unchanged (hh,hl,lh) -> bit-identical numerics.
#define ROW_B 64
#define ARR_B (128*ROW_B)
#define STAGE_B (4*ARR_B)
#define GSMEM_BYTES (3*STAGE_B)

template<int MODE>
__global__ __launch_bounds__(256, 2) void pgemm_kernel(const float* __restrict__ b0p,
                                                       const float* __restrict__ b1p,
                                                       const float* __restrict__ b2p,
                                                       float* __restrict__ outp)
{
    extern __shared__ uint32_t smu[];
    const uint32_t su = smem_u32(smu);

    const int tid  = threadIdx.x;
    const int lane = tid & 31;
    const int wid  = tid >> 5;
    const int wm = wid & 1;
    const int wn = wid >> 1;
    const int m0 = blockIdx.y << 7, n0 = blockIdx.x << 7;
    const int z = (MODE == 0) ? blockIdx.z : 3;

    const __nv_bfloat16* ahi = g_ahi + ((MODE == 0) ? (size_t)z * MK : 0) + (size_t)m0 * DIMC;
    const __nv_bfloat16* alo = g_alo + ((MODE == 0) ? (size_t)z * MK : 0) + (size_t)m0 * DIMC;
    const __nv_bfloat16* whi = g_whi + (size_t)z * DIMC * DIMC + (size_t)n0 * DIMC;
    const __nv_bfloat16* wlo = g_wlo + (size_t)z * DIMC * DIMC + (size_t)n0 * DIMC;
    const float* bias = (MODE == 1) ? b0p : (z == 0) ? b0p : (z == 1) ? b1p : b2p;

    float acc[4][4][4];
    #pragma unroll
    for (int i = 0; i < 4; i++)
        #pragma unroll
        for (int j = 0; j < 4; j++)
            #pragma unroll
            for (int r = 0; r < 4; r++) acc[i][j][r] = 0.f;

    const int a_row = (lane & 7) + 8 * ((lane >> 3) & 1);
    const int a_cs  = (lane >> 4) & 1;
    const int b_row = (lane & 7) + 8 * ((lane >> 4) & 1);
    const int b_cs  = (lane >> 3) & 1;
    const int a_sw = (a_row >> 1) & 3, b_sw = (b_row >> 1) & 3;
    uint32_t a_off[2], b_off[2];
    #pragma unroll
    for (int ks2 = 0; ks2 < 2; ks2++) {
        a_off[ks2] = (uint32_t)(a_row * ROW_B + (((ks2 << 1) | a_cs) ^ a_sw) * 16);
        b_off[ks2] = (uint32_t)(b_row * ROW_B + (((ks2 << 1) | b_cs) ^ b_sw) * 16);
    }

    const int l_row = tid >> 1;
    const int l_cb  = (tid & 1) << 1;
    const int l_sw  = (l_row >> 1) & 3;

    auto issue = [&](int c, int buf) {
        int k0 = c << 5;
        uint32_t base = su + (uint32_t)buf * STAGE_B;
        #pragma unroll
        for (int j = 0; j < 2; j++) {
            int ch = l_cb + j;
            size_t g = (size_t)l_row * DIMC + k0 + ch * 8;
            uint32_t so = (uint32_t)(l_row * ROW_B + (ch ^ l_sw) * 16);
            cpasync16(base + 0 * ARR_B + so, ahi + g);
            cpasync16(base + 1 * ARR_B + so, alo + g);
            cpasync16(base + 2 * ARR_B + so, whi + g);
            cpasync16(base + 3 * ARR_B + so, wlo + g);
        }
        asm volatile("cp.async.commit_group;");
    };

    issue(0, 0);
    issue(1, 1);
    for (int c = 0; c < 32; c++) {
        if (c < 31) { asm volatile("cp.async.wait_group 1;"); }
        else        { asm volatile("cp.async.wait_group 0;"); }
        __syncthreads();
        if (c + 2 < 32) issue(c + 2, (c + 2) % 3);

        uint32_t sb = su + (uint32_t)(c % 3) * STAGE_B;

        #pragma unroll
        for (int ks2 = 0; ks2 < 2; ks2++) {
            uint32_t ah[4][4], al[4][4], bh[2][4], bl[2][4];
            #pragma unroll
            for (int mt = 0; mt < 4; mt++) {
                uint32_t ab = sb + (uint32_t)((wm * 64 + mt * 16) * ROW_B) + a_off[ks2];
                ldsm4(ah[mt], ab);
                ldsm4(al[mt], ab + ARR_B);
            }
            #pragma unroll
            for (int p = 0; p < 2; p++) {
                uint32_t bb = sb + 2 * ARR_B + (uint32_t)((wn * 32 + p * 16) * ROW_B) + b_off[ks2];
                ldsm4(bh[p], bb);
                ldsm4(bl[p], bb + ARR_B);
            }
            // pass 0: Ah*Bh for all 16 tiles
            #pragma unroll
            for (int mt = 0; mt < 4; mt++)
                #pragma unroll
                for (int nt = 0; nt < 4; nt++) {
                    int p = nt >> 1, ix = (nt & 1) * 2;
                    mma16816(acc[mt][nt], ah[mt], bh[p][ix], bh[p][ix + 1]);
                }
            // pass 1: Ah*Bl
            #pragma unroll
            for (int mt = 0; mt < 4; mt++)
                #pragma unroll
                for (int nt = 0; nt < 4; nt++) {
                    int p = nt >> 1, ix = (nt & 1) * 2;
                    mma16816(acc[mt][nt], ah[mt], bl[p][ix], bl[p][ix + 1]);
                }
            // pass 2: Al*Bh
            #pragma unroll
            for (int mt = 0; mt < 4; mt++)
                #pragma unroll
                for (int nt = 0; nt < 4; nt++) {
                    int p = nt >> 1, ix = (nt & 1) * 2;
                    mma16816(acc[mt][nt], al[mt], bh[p][ix], bh[p][ix + 1]);
                }
        }
    }

    const int quad = lane >> 2, tc = lane & 3;
    #pragma unroll
    for (int mt = 0; mt < 4; mt++) {
        #pragma unroll
        for (int nt = 0; nt < 4; nt++) {
            #pragma unroll
            for (int half = 0; half < 2; half++) {
                int m = m0 + wm * 64 + mt * 16 + quad + half * 8;
                int n = n0 + wn * 32 + nt * 8 + tc * 2;
                float v0 = acc[mt][nt][half * 2]     + bias[n];
                float v1 = acc[mt][nt][half * 2 + 1] + bias[n + 1];
                if (MODE == 0) {
                    int b = m >> 11, t = m & (SEQ - 1);
                    int h = n >> 6, d = n & 63;
                    size_t base = ((size_t)(b * NH + h) * SEQ + t) * HD + d;
                    if (z == 2) {
                        g_v[base]     = v0;
                        g_v[base + 1] = v1;
                    } else {
                        float2 cs = g_rope[t * 32 + (d >> 1)];
                        float oe = v0 * cs.x - v1 * cs.y;
                        float oo = v0 * cs.y + v1 * cs.x;
                        uint32_t hi = packbf(oe, oo);
                        uint32_t lo = packbf(flo(oe), flo(oo));
                        if (z == 0) {
                            *(uint32_t*)(g_qhi + base) = hi;
                            *(uint32_t*)(g_qlo + base) = lo;
                        } else {
                            *(uint32_t*)(g_khi + base) = hi;
                            *(uint32_t*)(g_klo + base) = lo;
                        }
                    }
                } else {
                    size_t base = (size_t)m * DIMC + n;
                    outp[base]     = v0;
                    outp[base + 1] = v1;
                }
            }
        }
    }
}

// ---------------- attention: 3-stage cp.async, interleaved split-term MMAs ----------------
#define ASV 36
#define AARR (64*ASV)
#define ASTG (4*AARR)
#define ATT_SMEM_BYTES (3*ASTG*4)

__global__ __launch_bounds__(256, 2) void attn_kernel()
{
    extern __shared__ uint32_t smu[];
    const uint32_t su = smem_u32(smu);

    const int tid  = threadIdx.x;
    const int lane = tid & 31;
    const int wid  = tid >> 5;
    const int bh   = blockIdx.y;
    const int m0   = ((int)gridDim.x - 1 - (int)blockIdx.x) * 128;

    const size_t bhb = (size_t)bh * SEQ * HD;
    const __nv_bfloat16* Khi = g_khi + bhb;
    const __nv_bfloat16* Klo = g_klo + bhb;
    const __nv_bfloat16* Vthi = g_vthi + bhb;
    const __nv_bfloat16* Vtlo = g_vtlo + bhb;

    const uint32_t a_loff = (uint32_t)(((lane & 7) + 8 * ((lane >> 3) & 1)) * ASV * 4
                                       + ((lane >> 4) & 1) * 16);
    const uint32_t b_loff = (uint32_t)(((lane & 7) + 8 * ((lane >> 4) & 1)) * ASV * 4
                                       + ((lane >> 3) & 1) * 16);

    {
        const __nv_bfloat16* Qhi = g_qhi + bhb + (size_t)m0 * HD;
        const __nv_bfloat16* Qlo = g_qlo + bhb + (size_t)m0 * HD;
        #pragma unroll
        for (int j = 0; j < 4; j++) {
            int idx = tid + j * 256;
            int row = idx >> 3, seg = idx & 7;
            size_t g = (size_t)row * HD + seg * 8;
            int o = row * ASV + seg * 4;
            *(uint4*)(smu + o)        = *(const uint4*)(Qhi + g);
            *(uint4*)(smu + 4608 + o) = *(const uint4*)(Qlo + g);
        }
    }
    __syncthreads();
    uint32_t qh[4][4], ql[4][4];
    #pragma unroll
    for (int ks = 0; ks < 4; ks++) {
        uint32_t ab = su + (uint32_t)(wid * 16 * ASV * 4) + ks * 32 + a_loff;
        ldsm4(qh[ks], ab);
        ldsm4(ql[ks], ab + 4608 * 4);
    }
    __syncthreads();

    float oacc[8][4];
    #pragma unroll
    for (int nt = 0; nt < 8; nt++)
        #pragma unroll
        for (int e = 0; e < 4; e++) oacc[nt][e] = 0.f;
    float mr[2] = {-1e30f, -1e30f};
    float lr[2] = {0.f, 0.f};

    const int qr = lane >> 2, qc = lane & 3;
    const int rowbase = m0 + wid * 16;
    const int ntiles = m0 / 64 + 2;

    const int l_row = tid >> 2, l_seg = tid & 3;

    auto issue = [&](int tix, int buf) {
        int s0 = tix * 64;
        uint32_t base = su + (uint32_t)buf * ASTG * 4;
        #pragma unroll
        for (int ss = 0; ss < 2; ss++) {
            int seg = l_seg + ss * 4;
            uint32_t so = (uint32_t)(l_row * ASV + seg * 4) * 4;
            size_t gk = (size_t)(s0 + l_row) * HD + seg * 8;
            size_t gv = (size_t)l_row * SEQ + s0 + seg * 8;
            cpasync16(base + 0 * AARR * 4 + so, Khi + gk);
            cpasync16(base + 1 * AARR * 4 + so, Klo + gk);
            cpasync16(base + 2 * AARR * 4 + so, Vthi + gv);
            cpasync16(base + 3 * AARR * 4 + so, Vtlo + gv);
        }
        asm volatile("cp.async.commit_group;");
    };

    issue(0, 0);
    issue(1, 1);
    for (int tix = 0; tix < ntiles; tix++) {
        int s0 = tix * 64;
        if (tix + 1 < ntiles) { asm volatile("cp.async.wait_group 1;"); }
        else                  { asm volatile("cp.async.wait_group 0;"); }
        __syncthreads();
        if (tix + 2 < ntiles) issue(tix + 2, (tix + 2) % 3);

        if (s0 <= rowbase + 15) {
            uint32_t kvB = su + (uint32_t)(tix % 3) * ASTG * 4;

            float sacc[8][4];
            #pragma unroll
            for (int nt = 0; nt < 8; nt++)
                #pragma unroll
                for (int e = 0; e < 4; e++) sacc[nt][e] = 0.f;

            #pragma unroll
            for (int ks = 0; ks < 4; ks++) {
                #pragma unroll
                for (int p = 0; p < 4; p++) {
                    uint32_t bb = kvB + (uint32_t)(p * 16 * ASV * 4) + ks * 32 + b_loff;
                    uint32_t bhf[4], blf[4];
                    ldsm4(bhf, bb);
                    ldsm4(blf, bb + AARR * 4);
                    // per-acc order hh, hl, lh preserved; RAW distance 2
                    mma16816(sacc[2*p],   qh[ks], bhf[0], bhf[1]);
                    mma16816(sacc[2*p+1], qh[ks], bhf[2], bhf[3]);
                    mma16816(sacc[2*p],   qh[ks], blf[0], blf[1]);
                    mma16816(sacc[2*p+1], qh[ks], blf[2], blf[3]);
                    mma16816(sacc[2*p],   ql[ks], bhf[0], bhf[1]);
                    mma16816(sacc[2*p+1], ql[ks], bhf[2], bhf[3]);
                }
            }

            if (s0 + 63 > rowbase) {
                int rA = rowbase + qr, rB = rA + 8;
                #pragma unroll
                for (int nt = 0; nt < 8; nt++) {
                    int c0 = s0 + nt * 8 + qc * 2;
                    if (c0 > rA)     sacc[nt][0] = -1e30f;
                    if (c0 + 1 > rA) sacc[nt][1] = -1e30f;
                    if (c0 > rB)     sacc[nt][2] = -1e30f;
                    if (c0 + 1 > rB) sacc[nt][3] = -1e30f;
                }
            }

            float mxA = -1e30f, mxB = -1e30f;
            #pragma unroll
            for (int nt = 0; nt < 8; nt++) {
                mxA = fmaxf(mxA, fmaxf(sacc[nt][0], sacc[nt][1]));
                mxB = fmaxf(mxB, fmaxf(sacc[nt][2], sacc[nt][3]));
            }
            mxA = fmaxf(mxA, __shfl_xor_sync(0xffffffffu, mxA, 1));
            mxA = fmaxf(mxA, __shfl_xor_sync(0xffffffffu, mxA, 2));
            mxB = fmaxf(mxB, __shfl_xor_sync(0xffffffffu, mxB, 1));
            mxB = fmaxf(mxB, __shfl_xor_sync(0xffffffffu, mxB, 2));
            mxA *= 0.125f; mxB *= 0.125f;

            float mnA = fmaxf(mr[0], mxA), mnB = fmaxf(mr[1], mxB);
            float corrA = fexp2((mr[0] - mnA) * 1.44269504f);
            float corrB = fexp2((mr[1] - mnB) * 1.44269504f);
            mr[0] = mnA; mr[1] = mnB;
            float nbA = mnA * 1.44269504f, nbB = mnB * 1.44269504f;

            const float C1 = 0.125f * 1.44269504f;
            float suA = 0.f, suB = 0.f;
            #pragma unroll
            for (int nt = 0; nt < 8; nt++) {
                float p0 = fexp2(fmaf(sacc[nt][0], C1, -nbA));
                float p1 = fexp2(fmaf(sacc[nt][1], C1, -nbA));
                float p2 = fexp2(fmaf(sacc[nt][2], C1, -nbB));
                float p3 = fexp2(fmaf(sacc[nt][3], C1, -nbB));
                sacc[nt][0] = p0; sacc[nt][1] = p1;
                sacc[nt][2] = p2; sacc[nt][3] = p3;
                suA += p0 + p1; suB += p2 + p3;
            }
            suA += __shfl_xor_sync(0xffffffffu, suA, 1);
            suA += __shfl_xor_sync(0xffffffffu, suA, 2);
            suB += __shfl_xor_sync(0xffffffffu, suB, 1);
            suB += __shfl_xor_sync(0xffffffffu, suB, 2);
            lr[0] = lr[0] * corrA + suA;
            lr[1] = lr[1] * corrB + suB;
            #pragma unroll
            for (int nt = 0; nt < 8; nt++) {
                oacc[nt][0] *= corrA; oacc[nt][1] *= corrA;
                oacc[nt][2] *= corrB; oacc[nt][3] *= corrB;
            }

            uint32_t ph[4][4], pl[4][4];
            #pragma unroll
            for (int kk = 0; kk < 4; kk++) {
                float a0 = sacc[2*kk][0],   a1 = sacc[2*kk][1];
                float a2 = sacc[2*kk][2],   a3 = sacc[2*kk][3];
                float b0 = sacc[2*kk+1][0], b1 = sacc[2*kk+1][1];
                float b2 = sacc[2*kk+1][2], b3 = sacc[2*kk+1][3];
                ph[kk][0] = packbf(a0, a1); ph[kk][1] = packbf(a2, a3);
                ph[kk][2] = packbf(b0, b1); ph[kk][3] = packbf(b2, b3);
                pl[kk][0] = packbf(flo(a0), flo(a1)); pl[kk][1] = packbf(flo(a2), flo(a3));
                pl[kk][2] = packbf(flo(b0), flo(b1)); pl[kk][3] = packbf(flo(b2), flo(b3));
            }

            uint32_t vbB = kvB + 2 * AARR * 4;
            #pragma unroll
            for (int kk = 0; kk < 4; kk++) {
                #pragma unroll
                for (int p = 0; p < 4; p++) {
                    uint32_t vb = vbB + (uint32_t)(p * 16 * ASV * 4) + kk * 32 + b_loff;
                    uint32_t vhf[4], vlf[4];
                    ldsm4(vhf, vb);
                    ldsm4(vlf, vb + AARR * 4);
                    mma16816(oacc[2*p],   ph[kk], vhf[0], vhf[1]);
                    mma16816(oacc[2*p+1], ph[kk], vhf[2], vhf[3]);
                    mma16816(oacc[2*p],   ph[kk], vlf[0], vlf[1]);
                    mma16816(oacc[2*p+1], ph[kk], vlf[2], vlf[3]);
                    mma16816(oacc[2*p],   pl[kk], vhf[0], vhf[1]);
                    mma16816(oacc[2*p+1], pl[kk], vhf[2], vhf[3]);
                }
            }
        }
    }

    float ivA = 1.0f / lr[0], ivB = 1.0f / lr[1];
    int b = bh >> 4, h = bh & 15;
    int rA = rowbase + qr, rB = rA + 8;
    #pragma unroll
    for (int nt = 0; nt < 8; nt++) {
        int d = nt * 8 + qc * 2;
        size_t iA = ((size_t)(b * SEQ + rA)) * DIMC + h * HD + d;
        size_t iB = ((size_t)(b * SEQ + rB)) * DIMC + h * HD + d;
        float o0 = oacc[nt][0] * ivA, o1 = oacc[nt][1] * ivA;
        float o2 = oacc[nt][2] * ivB, o3 = oacc[nt][3] * ivB;
        *(uint32_t*)(g_ahi + iA) = packbf(o0, o1);
        *(uint32_t*)(g_alo + iA) = packbf(flo(o0), flo(o1));
        *(uint32_t*)(g_ahi + iB) = packbf(o2, o3);
        *(uint32_t*)(g_alo + iB) = packbf(flo(o2), flo(o3));
    }
}

// ---------------- launch ----------------
extern "C" void kernel_launch(void* const* d_in, const int* in_sizes, int n_in,
                              void* d_out, int out_size)
{
    const float* query = (const float*)d_in[0];
    const float* key   = (const float*)d_in[1];
    const float* value = (const float*)d_in[2];
    const float* Wq = (const float*)d_in[3];
    const float* bq = (const float*)d_in[4];
    const float* Wk = (const float*)d_in[5];
    const float* bk = (const float*)d_in[6];
    const float* Wv = (const float*)d_in[7];
    const float* bv = (const float*)d_in[8];
    const float* Wo = (const float*)d_in[9];
    const float* bo = (const float*)d_in[10];
    float* out = (float*)d_out;

    cudaFuncSetAttribute(pgemm_kernel<0>, cudaFuncAttributeMaxDynamicSharedMemorySize, GSMEM_BYTES);
    cudaFuncSetAttribute(pgemm_kernel<1>, cudaFuncAttributeMaxDynamicSharedMemorySize, GSMEM_BYTES);
    cudaFuncSetAttribute(attn_kernel, cudaFuncAttributeMaxDynamicSharedMemorySize, ATT_SMEM_BYTES);

    int n4 = BT * DIMC / 4;

    rope_table_kernel<<<SEQ * 32 / 256, 256>>>();
    asplit3_kernel<<<dim3(n4 / 256, 3), 256>>>((const float4*)query,
                                               (const float4*)key,
                                               (const float4*)value);
    wsplit4_kernel<<<dim3(32, 32, 4), dim3(32, 8)>>>(Wq, Wk, Wv, Wo);

    pgemm_kernel<0><<<dim3(8, 64, 3), 256, GSMEM_BYTES>>>(bq, bk, bv, nullptr);

    vtrans_kernel<<<dim3(SEQ / 64, BATCH * NH), 256>>>();

    attn_kernel<<<dim3(SEQ / 128, BATCH * NH), 256, ATT_SMEM_BYTES>>>();

    pgemm_kernel<1><<<dim3(8, 64, 1), 256, GSMEM_BYTES>>>(bo, nullptr, nullptr, out);
}

// round 13
// speedup vs baseline: 1.0268x; 1.0156x over previous
#include <cuda_runtime.h>
#include <cuda_bf16.h>
#include <math.h>
#include <stdint.h>

#define DIMC 1024
#define NH 16
#define HD 64
#define BATCH 4
#define SEQ 2048
#define BT (BATCH*SEQ)
#define MK ((size_t)BT*DIMC)
#define BHD ((size_t)BATCH*NH*SEQ*HD)

// ---------------- scratch (allocation-free) ----------------
__device__ float g_v[BHD];
__device__ __nv_bfloat16 g_qhi[BHD], g_qlo[BHD];
__device__ __nv_bfloat16 g_khi[BHD], g_klo[BHD];
__device__ __nv_bfloat16 g_vthi[BHD], g_vtlo[BHD];
__device__ __nv_bfloat16 g_ahi[3*MK];
__device__ __nv_bfloat16 g_alo[3*MK];
__device__ __nv_bfloat16 g_whi[4*(size_t)DIMC*DIMC];
__device__ __nv_bfloat16 g_wlo[4*(size_t)DIMC*DIMC];
__device__ float2 g_rope[SEQ*32];

// ---------------- PTX helpers ----------------
__device__ __forceinline__ uint32_t smem_u32(const void* p) {
    uint32_t a;
    asm("{ .reg .u64 t; cvta.to.shared.u64 t, %1; cvt.u32.u64 %0, t; }" : "=r"(a) : "l"(p));
    return a;
}
__device__ __forceinline__ void cpasync16(uint32_t saddr, const void* g) {
    asm volatile("cp.async.cg.shared.global [%0], [%1], 16;" :: "r"(saddr), "l"(g));
}
__device__ __forceinline__ void ldsm4(uint32_t* r, uint32_t addr) {
    asm volatile("ldmatrix.sync.aligned.m8n8.x4.shared.b16 {%0,%1,%2,%3}, [%4];"
                 : "=r"(r[0]), "=r"(r[1]), "=r"(r[2]), "=r"(r[3]) : "r"(addr));
}
__device__ __forceinline__ void mma16816(float* d, const uint32_t* a, uint32_t b0, uint32_t b1) {
    asm volatile("mma.sync.aligned.m16n8k16.row.col.f32.bf16.bf16.f32 "
                 "{%0,%1,%2,%3}, {%4,%5,%6,%7}, {%8,%9}, {%0,%1,%2,%3};"
                 : "+f"(d[0]), "+f"(d[1]), "+f"(d[2]), "+f"(d[3])
                 : "r"(a[0]), "r"(a[1]), "r"(a[2]), "r"(a[3]), "r"(b0), "r"(b1));
}
__device__ __forceinline__ uint32_t packbf(float a, float b) {
    __nv_bfloat162 t = __floats2bfloat162_rn(a, b);
    return *(uint32_t*)&t;
}
__device__ __forceinline__ float flo(float x) {
    return x - __bfloat162float(__float2bfloat16(x));
}
__device__ __forceinline__ float fexp2(float t) {
    t = fmaxf(t, -30.0f);
    float r = t + 12582912.0f;
    int n = __float_as_int(r) - 0x4B400000;
    float f = t - (r - 12582912.0f);
    float p = 1.3333558146e-3f;
    p = fmaf(p, f, 9.6181291077e-3f);
    p = fmaf(p, f, 5.5504108664e-2f);
    p = fmaf(p, f, 2.4022650696e-1f);
    p = fmaf(p, f, 6.9314718056e-1f);
    p = fmaf(p, f, 1.0f);
    return __int_as_float(__float_as_int(p) + (n << 23));
}

// ---------------- helper kernels ----------------
__global__ __launch_bounds__(256) void rope_table_kernel() {
    int idx = blockIdx.x * 256 + threadIdx.x;
    int t = idx >> 5, f = idx & 31;
    double invf = 1.0 / pow(10000.0, (double)(2 * f) / 64.0);
    float ang = (float)t * (float)invf;
    g_rope[idx] = make_float2((float)cos((double)ang), (float)sin((double)ang));
}

__global__ __launch_bounds__(256) void asplit3_kernel(const float4* __restrict__ q,
                                                      const float4* __restrict__ k,
                                                      const float4* __restrict__ v) {
    int z = blockIdx.y;
    const float4* src = (z == 0) ? q : (z == 1) ? k : v;
    size_t i = blockIdx.x * 256 + threadIdx.x;
    float4 val = src[i];
    float vv[4] = {val.x, val.y, val.z, val.w};
    __nv_bfloat16 h[4], l[4];
    #pragma unroll
    for (int j = 0; j < 4; j++) {
        h[j] = __float2bfloat16(vv[j]);
        l[j] = __float2bfloat16(vv[j] - __bfloat162float(h[j]));
    }
    size_t o = z * MK + 4 * i;
    *(uint2*)(g_ahi + o) = *(uint2*)h;
    *(uint2*)(g_alo + o) = *(uint2*)l;
}

__global__ __launch_bounds__(256) void wsplit4_kernel(const float* __restrict__ Wq,
                                                      const float* __restrict__ Wk,
                                                      const float* __restrict__ Wv,
                                                      const float* __restrict__ Wo) {
    __shared__ float tile[32][33];
    int z = blockIdx.z;
    const float* W = (z == 0) ? Wq : (z == 1) ? Wk : (z == 2) ? Wv : Wo;
    size_t wof = (size_t)z * DIMC * DIMC;
    int n0 = blockIdx.x * 32, k0 = blockIdx.y * 32;
    int x = threadIdx.x, y0 = threadIdx.y;
    for (int j = y0; j < 32; j += 8)
        tile[j][x] = W[(size_t)(k0 + j) * DIMC + n0 + x];
    __syncthreads();
    for (int j = y0; j < 32; j += 8) {
        float v = tile[x][j];
        __nv_bfloat16 h = __float2bfloat16(v);
        size_t o = wof + (size_t)(n0 + j) * DIMC + k0 + x;
        g_whi[o] = h;
        g_wlo[o] = __float2bfloat16(v - __bfloat162float(h));
    }
}

__global__ __launch_bounds__(256) void vtrans_kernel() {
    __shared__ float tile[64][65];
    int s0 = blockIdx.x * 64;
    int bh = blockIdx.y;
    const float* Vb = g_v + (size_t)bh * SEQ * HD;
    int tid = threadIdx.x;
    #pragma unroll
    for (int j = 0; j < 4; j++) {
        int idx = tid + j * 256;
        int r = idx >> 4, c4 = (idx & 15) << 2;
        float4 v = *(const float4*)(Vb + (size_t)(s0 + r) * HD + c4);
        tile[c4 + 0][r] = v.x; tile[c4 + 1][r] = v.y;
        tile[c4 + 2][r] = v.z; tile[c4 + 3][r] = v.w;
    }
    __syncthreads();
    size_t ob = (size_t)bh * HD * SEQ + s0;
    #pragma unroll
    for (int j = 0; j < 8; j++) {
        int u = tid + j * 256;
        int d = u >> 5, sp = u & 31;
        float e = tile[d][2 * sp], o = tile[d][2 * sp + 1];
        *(uint32_t*)(g_vthi + ob + (size_t)d * SEQ + 2 * sp) = packbf(e, o);
        *(uint32_t*)(g_vtlo + ob + (size_t)d * SEQ + 2 * sp) = packbf(flo(e), flo(o));
    }
}

// ---------------- 3-stage cp.async HMMA GEMM (unchanged, proven) ----------------
#define ROW_B 64
#define ARR_B (128*ROW_B)
#define STAGE_B (4*ARR_B)
#define GSMEM_BYTES (3*STAGE_B)

template<int MODE>
__global__ __launch_bounds__(256, 2) void pgemm_kernel(const float* __restrict__ b0p,
                                                       const float* __restrict__ b1p,
                                                       const float* __restrict__ b2p,
                                                       float* __restrict__ outp)
{
    extern __shared__ uint32_t smu[];
    const uint32_t su = smem_u32(smu);

    const int tid  = threadIdx.x;
    const int lane = tid & 31;
    const int wid  = tid >> 5;
    const int wm = wid & 1;
    const int wn = wid >> 1;
    const int m0 = blockIdx.y << 7, n0 = blockIdx.x << 7;
    const int z = (MODE == 0) ? blockIdx.z : 3;

    const __nv_bfloat16* ahi = g_ahi + ((MODE == 0) ? (size_t)z * MK : 0) + (size_t)m0 * DIMC;
    const __nv_bfloat16* alo = g_alo + ((MODE == 0) ? (size_t)z * MK : 0) + (size_t)m0 * DIMC;
    const __nv_bfloat16* whi = g_whi + (size_t)z * DIMC * DIMC + (size_t)n0 * DIMC;
    const __nv_bfloat16* wlo = g_wlo + (size_t)z * DIMC * DIMC + (size_t)n0 * DIMC;
    const float* bias = (MODE == 1) ? b0p : (z == 0) ? b0p : (z == 1) ? b1p : b2p;

    float acc[4][4][4];
    #pragma unroll
    for (int i = 0; i < 4; i++)
        #pragma unroll
        for (int j = 0; j < 4; j++)
            #pragma unroll
            for (int r = 0; r < 4; r++) acc[i][j][r] = 0.f;

    const int a_row = (lane & 7) + 8 * ((lane >> 3) & 1);
    const int a_cs  = (lane >> 4) & 1;
    const int b_row = (lane & 7) + 8 * ((lane >> 4) & 1);
    const int b_cs  = (lane >> 3) & 1;
    const int a_sw = (a_row >> 1) & 3, b_sw = (b_row >> 1) & 3;
    uint32_t a_off[2], b_off[2];
    #pragma unroll
    for (int ks2 = 0; ks2 < 2; ks2++) {
        a_off[ks2] = (uint32_t)(a_row * ROW_B + (((ks2 << 1) | a_cs) ^ a_sw) * 16);
        b_off[ks2] = (uint32_t)(b_row * ROW_B + (((ks2 << 1) | b_cs) ^ b_sw) * 16);
    }

    const int l_row = tid >> 1;
    const int l_cb  = (tid & 1) << 1;
    const int l_sw  = (l_row >> 1) & 3;

    auto issue = [&](int c, int buf) {
        int k0 = c << 5;
        uint32_t base = su + (uint32_t)buf * STAGE_B;
        #pragma unroll
        for (int j = 0; j < 2; j++) {
            int ch = l_cb + j;
            size_t g = (size_t)l_row * DIMC + k0 + ch * 8;
            uint32_t so = (uint32_t)(l_row * ROW_B + (ch ^ l_sw) * 16);
            cpasync16(base + 0 * ARR_B + so, ahi + g);
            cpasync16(base + 1 * ARR_B + so, alo + g);
            cpasync16(base + 2 * ARR_B + so, whi + g);
            cpasync16(base + 3 * ARR_B + so, wlo + g);
        }
        asm volatile("cp.async.commit_group;");
    };

    issue(0, 0);
    issue(1, 1);
    for (int c = 0; c < 32; c++) {
        if (c < 31) { asm volatile("cp.async.wait_group 1;"); }
        else        { asm volatile("cp.async.wait_group 0;"); }
        __syncthreads();
        if (c + 2 < 32) issue(c + 2, (c + 2) % 3);

        uint32_t sb = su + (uint32_t)(c % 3) * STAGE_B;

        #pragma unroll
        for (int ks2 = 0; ks2 < 2; ks2++) {
            uint32_t ah[4][4], al[4][4], bh[2][4], bl[2][4];
            #pragma unroll
            for (int mt = 0; mt < 4; mt++) {
                uint32_t ab = sb + (uint32_t)((wm * 64 + mt * 16) * ROW_B) + a_off[ks2];
                ldsm4(ah[mt], ab);
                ldsm4(al[mt], ab + ARR_B);
            }
            #pragma unroll
            for (int p = 0; p < 2; p++) {
                uint32_t bb = sb + 2 * ARR_B + (uint32_t)((wn * 32 + p * 16) * ROW_B) + b_off[ks2];
                ldsm4(bh[p], bb);
                ldsm4(bl[p], bb + ARR_B);
            }
            #pragma unroll
            for (int mt = 0; mt < 4; mt++)
                #pragma unroll
                for (int nt = 0; nt < 4; nt++) {
                    int p = nt >> 1, ix = (nt & 1) * 2;
                    mma16816(acc[mt][nt], ah[mt], bh[p][ix], bh[p][ix + 1]);
                }
            #pragma unroll
            for (int mt = 0; mt < 4; mt++)
                #pragma unroll
                for (int nt = 0; nt < 4; nt++) {
                    int p = nt >> 1, ix = (nt & 1) * 2;
                    mma16816(acc[mt][nt], ah[mt], bl[p][ix], bl[p][ix + 1]);
                }
            #pragma unroll
            for (int mt = 0; mt < 4; mt++)
                #pragma unroll
                for (int nt = 0; nt < 4; nt++) {
                    int p = nt >> 1, ix = (nt & 1) * 2;
                    mma16816(acc[mt][nt], al[mt], bh[p][ix], bh[p][ix + 1]);
                }
        }
    }

    const int quad = lane >> 2, tc = lane & 3;
    #pragma unroll
    for (int mt = 0; mt < 4; mt++) {
        #pragma unroll
        for (int nt = 0; nt < 4; nt++) {
            #pragma unroll
            for (int half = 0; half < 2; half++) {
                int m = m0 + wm * 64 + mt * 16 + quad + half * 8;
                int n = n0 + wn * 32 + nt * 8 + tc * 2;
                float v0 = acc[mt][nt][half * 2]     + bias[n];
                float v1 = acc[mt][nt][half * 2 + 1] + bias[n + 1];
                if (MODE == 0) {
                    int b = m >> 11, t = m & (SEQ - 1);
                    int h = n >> 6, d = n & 63;
                    size_t base = ((size_t)(b * NH + h) * SEQ + t) * HD + d;
                    if (z == 2) {
                        g_v[base]     = v0;
                        g_v[base + 1] = v1;
                    } else {
                        float2 cs = g_rope[t * 32 + (d >> 1)];
                        float oe = v0 * cs.x - v1 * cs.y;
                        float oo = v0 * cs.y + v1 * cs.x;
                        uint32_t hi = packbf(oe, oo);
                        uint32_t lo = packbf(flo(oe), flo(oo));
                        if (z == 0) {
                            *(uint32_t*)(g_qhi + base) = hi;
                            *(uint32_t*)(g_qlo + base) = lo;
                        } else {
                            *(uint32_t*)(g_khi + base) = hi;
                            *(uint32_t*)(g_klo + base) = lo;
                        }
                    }
                } else {
                    size_t base = (size_t)m * DIMC + n;
                    outp[base]     = v0;
                    outp[base + 1] = v1;
                }
            }
        }
    }
}

// ---------------- attention: unnormalized-exp softmax (no max tracking) ----------------
// O = sum P*V, l = sum P with P = exp2(s*C1); O/l == softmax(s)V exactly.
// Removes per-tile max/corr/shfl chains; l reduced once in the epilogue.
#define ASV 36
#define AARR (64*ASV)
#define ASTG (4*AARR)
#define ATT_SMEM_BYTES (3*ASTG*4)

__global__ __launch_bounds__(256, 2) void attn_kernel()
{
    extern __shared__ uint32_t smu[];
    const uint32_t su = smem_u32(smu);

    const int tid  = threadIdx.x;
    const int lane = tid & 31;
    const int wid  = tid >> 5;
    const int bh   = blockIdx.y;
    const int m0   = ((int)gridDim.x - 1 - (int)blockIdx.x) * 128;

    const size_t bhb = (size_t)bh * SEQ * HD;
    const __nv_bfloat16* Khi = g_khi + bhb;
    const __nv_bfloat16* Klo = g_klo + bhb;
    const __nv_bfloat16* Vthi = g_vthi + bhb;
    const __nv_bfloat16* Vtlo = g_vtlo + bhb;

    const uint32_t a_loff = (uint32_t)(((lane & 7) + 8 * ((lane >> 3) & 1)) * ASV * 4
                                       + ((lane >> 4) & 1) * 16);
    const uint32_t b_loff = (uint32_t)(((lane & 7) + 8 * ((lane >> 4) & 1)) * ASV * 4
                                       + ((lane >> 3) & 1) * 16);

    {
        const __nv_bfloat16* Qhi = g_qhi + bhb + (size_t)m0 * HD;
        const __nv_bfloat16* Qlo = g_qlo + bhb + (size_t)m0 * HD;
        #pragma unroll
        for (int j = 0; j < 4; j++) {
            int idx = tid + j * 256;
            int row = idx >> 3, seg = idx & 7;
            size_t g = (size_t)row * HD + seg * 8;
            int o = row * ASV + seg * 4;
            *(uint4*)(smu + o)        = *(const uint4*)(Qhi + g);
            *(uint4*)(smu + 4608 + o) = *(const uint4*)(Qlo + g);
        }
    }
    __syncthreads();
    uint32_t qh[4][4], ql[4][4];
    #pragma unroll
    for (int ks = 0; ks < 4; ks++) {
        uint32_t ab = su + (uint32_t)(wid * 16 * ASV * 4) + ks * 32 + a_loff;
        ldsm4(qh[ks], ab);
        ldsm4(ql[ks], ab + 4608 * 4);
    }
    __syncthreads();

    float oacc[8][4];
    #pragma unroll
    for (int nt = 0; nt < 8; nt++)
        #pragma unroll
        for (int e = 0; e < 4; e++) oacc[nt][e] = 0.f;
    float lr[2] = {0.f, 0.f};   // per-lane partial sums of P

    const int qr = lane >> 2, qc = lane & 3;
    const int rowbase = m0 + wid * 16;
    const int ntiles = m0 / 64 + 2;

    const int l_row = tid >> 2, l_seg = tid & 3;

    auto issue = [&](int tix, int buf) {
        int s0 = tix * 64;
        uint32_t base = su + (uint32_t)buf * ASTG * 4;
        #pragma unroll
        for (int ss = 0; ss < 2; ss++) {
            int seg = l_seg + ss * 4;
            uint32_t so = (uint32_t)(l_row * ASV + seg * 4) * 4;
            size_t gk = (size_t)(s0 + l_row) * HD + seg * 8;
            size_t gv = (size_t)l_row * SEQ + s0 + seg * 8;
            cpasync16(base + 0 * AARR * 4 + so, Khi + gk);
            cpasync16(base + 1 * AARR * 4 + so, Klo + gk);
            cpasync16(base + 2 * AARR * 4 + so, Vthi + gv);
            cpasync16(base + 3 * AARR * 4 + so, Vtlo + gv);
        }
        asm volatile("cp.async.commit_group;");
    };

    issue(0, 0);
    issue(1, 1);
    for (int tix = 0; tix < ntiles; tix++) {
        int s0 = tix * 64;
        if (tix + 1 < ntiles) { asm volatile("cp.async.wait_group 1;"); }
        else                  { asm volatile("cp.async.wait_group 0;"); }
        __syncthreads();
        if (tix + 2 < ntiles) issue(tix + 2, (tix + 2) % 3);

        if (s0 <= rowbase + 15) {
            uint32_t kvB = su + (uint32_t)(tix % 3) * ASTG * 4;

            float sacc[8][4];
            #pragma unroll
            for (int nt = 0; nt < 8; nt++)
                #pragma unroll
                for (int e = 0; e < 4; e++) sacc[nt][e] = 0.f;

            #pragma unroll
            for (int ks = 0; ks < 4; ks++) {
                #pragma unroll
                for (int p = 0; p < 4; p++) {
                    uint32_t bb = kvB + (uint32_t)(p * 16 * ASV * 4) + ks * 32 + b_loff;
                    uint32_t bhf[4], blf[4];
                    ldsm4(bhf, bb);
                    ldsm4(blf, bb + AARR * 4);
                    mma16816(sacc[2*p],   qh[ks], bhf[0], bhf[1]);
                    mma16816(sacc[2*p+1], qh[ks], bhf[2], bhf[3]);
                    mma16816(sacc[2*p],   qh[ks], blf[0], blf[1]);
                    mma16816(sacc[2*p+1], qh[ks], blf[2], blf[3]);
                    mma16816(sacc[2*p],   ql[ks], bhf[0], bhf[1]);
                    mma16816(sacc[2*p+1], ql[ks], bhf[2], bhf[3]);
                }
            }

            if (s0 + 63 > rowbase) {
                int rA = rowbase + qr, rB = rA + 8;
                #pragma unroll
                for (int nt = 0; nt < 8; nt++) {
                    int c0 = s0 + nt * 8 + qc * 2;
                    if (c0 > rA)     sacc[nt][0] = -1e30f;
                    if (c0 + 1 > rA) sacc[nt][1] = -1e30f;
                    if (c0 > rB)     sacc[nt][2] = -1e30f;
                    if (c0 + 1 > rB) sacc[nt][3] = -1e30f;
                }
            }

            // ---- unnormalized exp (no max subtraction, no per-tile reductions) ----
            const float C1 = 0.125f * 1.44269504f;   // score scale * log2e
            #pragma unroll
            for (int nt = 0; nt < 8; nt++) {
                float p0 = fexp2(sacc[nt][0] * C1);
                float p1 = fexp2(sacc[nt][1] * C1);
                float p2 = fexp2(sacc[nt][2] * C1);
                float p3 = fexp2(sacc[nt][3] * C1);
                sacc[nt][0] = p0; sacc[nt][1] = p1;
                sacc[nt][2] = p2; sacc[nt][3] = p3;
                lr[0] += p0 + p1;
                lr[1] += p2 + p3;
            }

            // ---- P -> bf16 hi/lo A-fragments ----
            uint32_t ph[4][4], pl[4][4];
            #pragma unroll
            for (int kk = 0; kk < 4; kk++) {
                float a0 = sacc[2*kk][0],   a1 = sacc[2*kk][1];
                float a2 = sacc[2*kk][2],   a3 = sacc[2*kk][3];
                float b0 = sacc[2*kk+1][0], b1 = sacc[2*kk+1][1];
                float b2 = sacc[2*kk+1][2], b3 = sacc[2*kk+1][3];
                ph[kk][0] = packbf(a0, a1); ph[kk][1] = packbf(a2, a3);
                ph[kk][2] = packbf(b0, b1); ph[kk][3] = packbf(b2, b3);
                pl[kk][0] = packbf(flo(a0), flo(a1)); pl[kk][1] = packbf(flo(a2), flo(a3));
                pl[kk][2] = packbf(flo(b0), flo(b1)); pl[kk][3] = packbf(flo(b2), flo(b3));
            }

            // ---- O += P V ----
            uint32_t vbB = kvB + 2 * AARR * 4;
            #pragma unroll
            for (int kk = 0; kk < 4; kk++) {
                #pragma unroll
                for (int p = 0; p < 4; p++) {
                    uint32_t vb = vbB + (uint32_t)(p * 16 * ASV * 4) + kk * 32 + b_loff;
                    uint32_t vhf[4], vlf[4];
                    ldsm4(vhf, vb);
                    ldsm4(vlf, vb + AARR * 4);
                    mma16816(oacc[2*p],   ph[kk], vhf[0], vhf[1]);
                    mma16816(oacc[2*p+1], ph[kk], vhf[2], vhf[3]);
                    mma16816(oacc[2*p],   ph[kk], vlf[0], vlf[1]);
                    mma16816(oacc[2*p+1], ph[kk], vlf[2], vlf[3]);
                    mma16816(oacc[2*p],   pl[kk], vhf[0], vhf[1]);
                    mma16816(oacc[2*p+1], pl[kk], vhf[2], vhf[3]);
                }
            }
        }
    }

    // ---- single l reduction across the 4 lanes sharing each row ----
    lr[0] += __shfl_xor_sync(0xffffffffu, lr[0], 1);
    lr[0] += __shfl_xor_sync(0xffffffffu, lr[0], 2);
    lr[1] += __shfl_xor_sync(0xffffffffu, lr[1], 1);
    lr[1] += __shfl_xor_sync(0xffffffffu, lr[1], 2);

    float ivA = 1.0f / lr[0], ivB = 1.0f / lr[1];
    int b = bh >> 4, h = bh & 15;
    int rA = rowbase + qr, rB = rA + 8;
    #pragma unroll
    for (int nt = 0; nt < 8; nt++) {
        int d = nt * 8 + qc * 2;
        size_t iA = ((size_t)(b * SEQ + rA)) * DIMC + h * HD + d;
        size_t iB = ((size_t)(b * SEQ + rB)) * DIMC + h * HD + d;
        float o0 = oacc[nt][0] * ivA, o1 = oacc[nt][1] * ivA;
        float o2 = oacc[nt][2] * ivB, o3 = oacc[nt][3] * ivB;
        *(uint32_t*)(g_ahi + iA) = packbf(o0, o1);
        *(uint32_t*)(g_alo + iA) = packbf(flo(o0), flo(o1));
        *(uint32_t*)(g_ahi + iB) = packbf(o2, o3);
        *(uint32_t*)(g_alo + iB) = packbf(flo(o2), flo(o3));
    }
}

// ---------------- launch ----------------
extern "C" void kernel_launch(void* const* d_in, const int* in_sizes, int n_in,
                              void* d_out, int out_size)
{
    const float* query = (const float*)d_in[0];
    const float* key   = (const float*)d_in[1];
    const float* value = (const float*)d_in[2];
    const float* Wq = (const float*)d_in[3];
    const float* bq = (const float*)d_in[4];
    const float* Wk = (const float*)d_in[5];
    const float* bk = (const float*)d_in[6];
    const float* Wv = (const float*)d_in[7];
    const float* bv = (const float*)d_in[8];
    const float* Wo = (const float*)d_in[9];
    const float* bo = (const float*)d_in[10];
    float* out = (float*)d_out;

    cudaFuncSetAttribute(pgemm_kernel<0>, cudaFuncAttributeMaxDynamicSharedMemorySize, GSMEM_BYTES);
    cudaFuncSetAttribute(pgemm_kernel<1>, cudaFuncAttributeMaxDynamicSharedMemorySize, GSMEM_BYTES);
    cudaFuncSetAttribute(attn_kernel, cudaFuncAttributeMaxDynamicSharedMemorySize, ATT_SMEM_BYTES);

    int n4 = BT * DIMC / 4;

    rope_table_kernel<<<SEQ * 32 / 256, 256>>>();
    asplit3_kernel<<<dim3(n4 / 256, 3), 256>>>((const float4*)query,
                                               (const float4*)key,
                                               (const float4*)value);
    wsplit4_kernel<<<dim3(32, 32, 4), dim3(32, 8)>>>(Wq, Wk, Wv, Wo);

    pgemm_kernel<0><<<dim3(8, 64, 3), 256, GSMEM_BYTES>>>(bq, bk, bv, nullptr);

    vtrans_kernel<<<dim3(SEQ / 64, BATCH * NH), 256>>>();

    attn_kernel<<<dim3(SEQ / 128, BATCH * NH), 256, ATT_SMEM_BYTES>>>();

    pgemm_kernel<1><<<dim3(8, 64, 1), 256, GSMEM_BYTES>>>(bo, nullptr, nullptr, out);
}

// round 14
// speedup vs baseline: 1.4055x; 1.3688x over previous
#include <cuda_runtime.h>
#include <cuda_fp16.h>
#include <math.h>
#include <stdint.h>

#define DIMC 1024
#define NH 16
#define HD 64
#define BATCH 4
#define SEQ 2048
#define BT (BATCH*SEQ)
#define MK ((size_t)BT*DIMC)
#define BHD ((size_t)BATCH*NH*SEQ*HD)

// ---------------- scratch (allocation-free) ----------------
__device__ float g_v[BHD];
__device__ __half g_qhi[BHD], g_qlo[BHD];        // RoPE'd Q hi/lo
__device__ __half g_khi[BHD];                    // RoPE'd K (fp16, B-side)
__device__ __half g_vthi[BHD];                   // V^T (fp16, B-side)
__device__ __half g_ahi[3*MK];                   // GEMM A slots hi
__device__ __half g_alo[3*MK];                   // GEMM A slots lo
__device__ __half g_whi[4*(size_t)DIMC*DIMC];    // W (fp16, B-side)
__device__ float2 g_rope[SEQ*32];

// ---------------- PTX helpers ----------------
__device__ __forceinline__ uint32_t smem_u32(const void* p) {
    uint32_t a;
    asm("{ .reg .u64 t; cvta.to.shared.u64 t, %1; cvt.u32.u64 %0, t; }" : "=r"(a) : "l"(p));
    return a;
}
__device__ __forceinline__ void cpasync16(uint32_t saddr, const void* g) {
    asm volatile("cp.async.cg.shared.global [%0], [%1], 16;" :: "r"(saddr), "l"(g));
}
__device__ __forceinline__ void ldsm4(uint32_t* r, uint32_t addr) {
    asm volatile("ldmatrix.sync.aligned.m8n8.x4.shared.b16 {%0,%1,%2,%3}, [%4];"
                 : "=r"(r[0]), "=r"(r[1]), "=r"(r[2]), "=r"(r[3]) : "r"(addr));
}
__device__ __forceinline__ void mma16816(float* d, const uint32_t* a, uint32_t b0, uint32_t b1) {
    asm volatile("mma.sync.aligned.m16n8k16.row.col.f32.f16.f16.f32 "
                 "{%0,%1,%2,%3}, {%4,%5,%6,%7}, {%8,%9}, {%0,%1,%2,%3};"
                 : "+f"(d[0]), "+f"(d[1]), "+f"(d[2]), "+f"(d[3])
                 : "r"(a[0]), "r"(a[1]), "r"(a[2]), "r"(a[3]), "r"(b0), "r"(b1));
}
__device__ __forceinline__ uint32_t packh(float a, float b) {
    __half2 t = __floats2half2_rn(a, b);
    return *(uint32_t*)&t;
}
__device__ __forceinline__ float floh(float x) {
    return x - __half2float(__float2half_rn(x));
}
__device__ __forceinline__ float fexp2(float t) {
    t = fmaxf(t, -30.0f);
    float r = t + 12582912.0f;
    int n = __float_as_int(r) - 0x4B400000;
    float f = t - (r - 12582912.0f);
    float p = 1.3333558146e-3f;
    p = fmaf(p, f, 9.6181291077e-3f);
    p = fmaf(p, f, 5.5504108664e-2f);
    p = fmaf(p, f, 2.4022650696e-1f);
    p = fmaf(p, f, 6.9314718056e-1f);
    p = fmaf(p, f, 1.0f);
    return __int_as_float(__float_as_int(p) + (n << 23));
}

// ---------------- helper kernels ----------------
__global__ __launch_bounds__(256) void rope_table_kernel() {
    int idx = blockIdx.x * 256 + threadIdx.x;
    int t = idx >> 5, f = idx & 31;
    double invf = 1.0 / pow(10000.0, (double)(2 * f) / 64.0);
    float ang = (float)t * (float)invf;
    g_rope[idx] = make_float2((float)cos((double)ang), (float)sin((double)ang));
}

__global__ __launch_bounds__(256) void asplit3_kernel(const float4* __restrict__ q,
                                                      const float4* __restrict__ k,
                                                      const float4* __restrict__ v) {
    int z = blockIdx.y;
    const float4* src = (z == 0) ? q : (z == 1) ? k : v;
    size_t i = blockIdx.x * 256 + threadIdx.x;
    float4 val = src[i];
    float vv[4] = {val.x, val.y, val.z, val.w};
    __half h[4], l[4];
    #pragma unroll
    for (int j = 0; j < 4; j++) {
        h[j] = __float2half_rn(vv[j]);
        l[j] = __float2half_rn(vv[j] - __half2float(h[j]));
    }
    size_t o = z * MK + 4 * i;
    *(uint2*)(g_ahi + o) = *(uint2*)h;
    *(uint2*)(g_alo + o) = *(uint2*)l;
}

// W [K,N] fp32 -> transposed fp16 [N,K], slot z (B-side: hi only)
__global__ __launch_bounds__(256) void wsplit4_kernel(const float* __restrict__ Wq,
                                                      const float* __restrict__ Wk,
                                                      const float* __restrict__ Wv,
                                                      const float* __restrict__ Wo) {
    __shared__ float tile[32][33];
    int z = blockIdx.z;
    const float* W = (z == 0) ? Wq : (z == 1) ? Wk : (z == 2) ? Wv : Wo;
    size_t wof = (size_t)z * DIMC * DIMC;
    int n0 = blockIdx.x * 32, k0 = blockIdx.y * 32;
    int x = threadIdx.x, y0 = threadIdx.y;
    for (int j = y0; j < 32; j += 8)
        tile[j][x] = W[(size_t)(k0 + j) * DIMC + n0 + x];
    __syncthreads();
    for (int j = y0; j < 32; j += 8)
        g_whi[wof + (size_t)(n0 + j) * DIMC + k0 + x] = __float2half_rn(tile[x][j]);
}

// V [B,H,S,D] fp32 -> V^T [B,H,D,S] fp16 (B-side: hi only)
__global__ __launch_bounds__(256) void vtrans_kernel() {
    __shared__ float tile[64][65];
    int s0 = blockIdx.x * 64;
    int bh = blockIdx.y;
    const float* Vb = g_v + (size_t)bh * SEQ * HD;
    int tid = threadIdx.x;
    #pragma unroll
    for (int j = 0; j < 4; j++) {
        int idx = tid + j * 256;
        int r = idx >> 4, c4 = (idx & 15) << 2;
        float4 v = *(const float4*)(Vb + (size_t)(s0 + r) * HD + c4);
        tile[c4 + 0][r] = v.x; tile[c4 + 1][r] = v.y;
        tile[c4 + 2][r] = v.z; tile[c4 + 3][r] = v.w;
    }
    __syncthreads();
    size_t ob = (size_t)bh * HD * SEQ + s0;
    #pragma unroll
    for (int j = 0; j < 8; j++) {
        int u = tid + j * 256;
        int d = u >> 5, sp = u & 31;
        *(uint32_t*)(g_vthi + ob + (size_t)d * SEQ + 2 * sp) =
            packh(tile[d][2 * sp], tile[d][2 * sp + 1]);
    }
}

// ---------------- 3-stage cp.async fp16 GEMM: C = (Ah+Al) * W16 ----------------
// 2 MMAs per tile. XOR-swizzled 64B rows. Arrays per stage: {Ahi, Alo, W}.
#define ROW_B 64
#define ARR_B (128*ROW_B)            // 8192 B
#define STAGE_B (3*ARR_B)            // 24576 B
#define GSMEM_BYTES (3*STAGE_B)      // 73728 B

template<int MODE>
__global__ __launch_bounds__(256, 2) void pgemm_kernel(const float* __restrict__ b0p,
                                                       const float* __restrict__ b1p,
                                                       const float* __restrict__ b2p,
                                                       float* __restrict__ outp)
{
    extern __shared__ uint32_t smu[];
    const uint32_t su = smem_u32(smu);

    const int tid  = threadIdx.x;
    const int lane = tid & 31;
    const int wid  = tid >> 5;
    const int wm = wid & 1;
    const int wn = wid >> 1;
    const int m0 = blockIdx.y << 7, n0 = blockIdx.x << 7;
    const int z = (MODE == 0) ? blockIdx.z : 3;

    const __half* ahi = g_ahi + ((MODE == 0) ? (size_t)z * MK : 0) + (size_t)m0 * DIMC;
    const __half* alo = g_alo + ((MODE == 0) ? (size_t)z * MK : 0) + (size_t)m0 * DIMC;
    const __half* whi = g_whi + (size_t)z * DIMC * DIMC + (size_t)n0 * DIMC;
    const float* bias = (MODE == 1) ? b0p : (z == 0) ? b0p : (z == 1) ? b1p : b2p;

    float acc[4][4][4];
    #pragma unroll
    for (int i = 0; i < 4; i++)
        #pragma unroll
        for (int j = 0; j < 4; j++)
            #pragma unroll
            for (int r = 0; r < 4; r++) acc[i][j][r] = 0.f;

    const int a_row = (lane & 7) + 8 * ((lane >> 3) & 1);
    const int a_cs  = (lane >> 4) & 1;
    const int b_row = (lane & 7) + 8 * ((lane >> 4) & 1);
    const int b_cs  = (lane >> 3) & 1;
    const int a_sw = (a_row >> 1) & 3, b_sw = (b_row >> 1) & 3;
    uint32_t a_off[2], b_off[2];
    #pragma unroll
    for (int ks2 = 0; ks2 < 2; ks2++) {
        a_off[ks2] = (uint32_t)(a_row * ROW_B + (((ks2 << 1) | a_cs) ^ a_sw) * 16);
        b_off[ks2] = (uint32_t)(b_row * ROW_B + (((ks2 << 1) | b_cs) ^ b_sw) * 16);
    }

    const int l_row = tid >> 1;
    const int l_cb  = (tid & 1) << 1;
    const int l_sw  = (l_row >> 1) & 3;

    auto issue = [&](int c, int buf) {
        int k0 = c << 5;
        uint32_t base = su + (uint32_t)buf * STAGE_B;
        #pragma unroll
        for (int j = 0; j < 2; j++) {
            int ch = l_cb + j;
            size_t g = (size_t)l_row * DIMC + k0 + ch * 8;
            uint32_t so = (uint32_t)(l_row * ROW_B + (ch ^ l_sw) * 16);
            cpasync16(base + 0 * ARR_B + so, ahi + g);
            cpasync16(base + 1 * ARR_B + so, alo + g);
            cpasync16(base + 2 * ARR_B + so, whi + g);
        }
        asm volatile("cp.async.commit_group;");
    };

    issue(0, 0);
    issue(1, 1);
    for (int c = 0; c < 32; c++) {
        if (c < 31) { asm volatile("cp.async.wait_group 1;"); }
        else        { asm volatile("cp.async.wait_group 0;"); }
        __syncthreads();
        if (c + 2 < 32) issue(c + 2, (c + 2) % 3);

        uint32_t sb = su + (uint32_t)(c % 3) * STAGE_B;

        #pragma unroll
        for (int ks2 = 0; ks2 < 2; ks2++) {
            uint32_t ah[4][4], al[4][4], bh[2][4];
            #pragma unroll
            for (int mt = 0; mt < 4; mt++) {
                uint32_t ab = sb + (uint32_t)((wm * 64 + mt * 16) * ROW_B) + a_off[ks2];
                ldsm4(ah[mt], ab);
                ldsm4(al[mt], ab + ARR_B);
            }
            #pragma unroll
            for (int p = 0; p < 2; p++) {
                uint32_t bb = sb + 2 * ARR_B + (uint32_t)((wn * 32 + p * 16) * ROW_B) + b_off[ks2];
                ldsm4(bh[p], bb);
            }
            // pass 0: Ah*W for all 16 tiles
            #pragma unroll
            for (int mt = 0; mt < 4; mt++)
                #pragma unroll
                for (int nt = 0; nt < 4; nt++) {
                    int p = nt >> 1, ix = (nt & 1) * 2;
                    mma16816(acc[mt][nt], ah[mt], bh[p][ix], bh[p][ix + 1]);
                }
            // pass 1: Al*W
            #pragma unroll
            for (int mt = 0; mt < 4; mt++)
                #pragma unroll
                for (int nt = 0; nt < 4; nt++) {
                    int p = nt >> 1, ix = (nt & 1) * 2;
                    mma16816(acc[mt][nt], al[mt], bh[p][ix], bh[p][ix + 1]);
                }
        }
    }

    const int quad = lane >> 2, tc = lane & 3;
    #pragma unroll
    for (int mt = 0; mt < 4; mt++) {
        #pragma unroll
        for (int nt = 0; nt < 4; nt++) {
            #pragma unroll
            for (int half = 0; half < 2; half++) {
                int m = m0 + wm * 64 + mt * 16 + quad + half * 8;
                int n = n0 + wn * 32 + nt * 8 + tc * 2;
                float v0 = acc[mt][nt][half * 2]     + bias[n];
                float v1 = acc[mt][nt][half * 2 + 1] + bias[n + 1];
                if (MODE == 0) {
                    int b = m >> 11, t = m & (SEQ - 1);
                    int h = n >> 6, d = n & 63;
                    size_t base = ((size_t)(b * NH + h) * SEQ + t) * HD + d;
                    if (z == 2) {
                        g_v[base]     = v0;
                        g_v[base + 1] = v1;
                    } else {
                        float2 cs = g_rope[t * 32 + (d >> 1)];
                        float oe = v0 * cs.x - v1 * cs.y;
                        float oo = v0 * cs.y + v1 * cs.x;
                        if (z == 0) {
                            *(uint32_t*)(g_qhi + base) = packh(oe, oo);
                            *(uint32_t*)(g_qlo + base) = packh(floh(oe), floh(oo));
                        } else {
                            *(uint32_t*)(g_khi + base) = packh(oe, oo);
                        }
                    }
                } else {
                    size_t base = (size_t)m * DIMC + n;
                    outp[base]     = v0;
                    outp[base + 1] = v1;
                }
            }
        }
    }
}

// ---------------- attention: fp16, 2-term A-side split, single-fp16 K/V ----------------
#define ASV 36
#define AARR (64*ASV)
#define ASTG (2*AARR)               // arrays per stage: {K, V}
#define ATT_SMEM_BYTES (3*ASTG*4)   // 55296

__global__ __launch_bounds__(256, 2) void attn_kernel()
{
    extern __shared__ uint32_t smu[];
    const uint32_t su = smem_u32(smu);

    const int tid  = threadIdx.x;
    const int lane = tid & 31;
    const int wid  = tid >> 5;
    const int bh   = blockIdx.y;
    const int m0   = ((int)gridDim.x - 1 - (int)blockIdx.x) * 128;

    const size_t bhb = (size_t)bh * SEQ * HD;
    const __half* Khi = g_khi + bhb;
    const __half* Vthi = g_vthi + bhb;

    const uint32_t a_loff = (uint32_t)(((lane & 7) + 8 * ((lane >> 3) & 1)) * ASV * 4
                                       + ((lane >> 4) & 1) * 16);
    const uint32_t b_loff = (uint32_t)(((lane & 7) + 8 * ((lane >> 4) & 1)) * ASV * 4
                                       + ((lane >> 3) & 1) * 16);

    // ---- prologue: stage Q tile (hi at 0, lo at 4608 u32), frags to regs ----
    {
        const __half* Qhi = g_qhi + bhb + (size_t)m0 * HD;
        const __half* Qlo = g_qlo + bhb + (size_t)m0 * HD;
        #pragma unroll
        for (int j = 0; j < 4; j++) {
            int idx = tid + j * 256;
            int row = idx >> 3, seg = idx & 7;
            size_t g = (size_t)row * HD + seg * 8;
            int o = row * ASV + seg * 4;
            *(uint4*)(smu + o)        = *(const uint4*)(Qhi + g);
            *(uint4*)(smu + 4608 + o) = *(const uint4*)(Qlo + g);
        }
    }
    __syncthreads();
    uint32_t qh[4][4], ql[4][4];
    #pragma unroll
    for (int ks = 0; ks < 4; ks++) {
        uint32_t ab = su + (uint32_t)(wid * 16 * ASV * 4) + ks * 32 + a_loff;
        ldsm4(qh[ks], ab);
        ldsm4(ql[ks], ab + 4608 * 4);
    }
    __syncthreads();

    float oacc[8][4];
    #pragma unroll
    for (int nt = 0; nt < 8; nt++)
        #pragma unroll
        for (int e = 0; e < 4; e++) oacc[nt][e] = 0.f;
    float lr[2] = {0.f, 0.f};

    const int qr = lane >> 2, qc = lane & 3;
    const int rowbase = m0 + wid * 16;
    const int ntiles = m0 / 64 + 2;

    const int l_row = tid >> 2, l_seg = tid & 3;

    auto issue = [&](int tix, int buf) {
        int s0 = tix * 64;
        uint32_t base = su + (uint32_t)buf * ASTG * 4;
        #pragma unroll
        for (int ss = 0; ss < 2; ss++) {
            int seg = l_seg + ss * 4;
            uint32_t so = (uint32_t)(l_row * ASV + seg * 4) * 4;
            size_t gk = (size_t)(s0 + l_row) * HD + seg * 8;
            size_t gv = (size_t)l_row * SEQ + s0 + seg * 8;
            cpasync16(base + 0 * AARR * 4 + so, Khi + gk);
            cpasync16(base + 1 * AARR * 4 + so, Vthi + gv);
        }
        asm volatile("cp.async.commit_group;");
    };

    issue(0, 0);
    issue(1, 1);
    for (int tix = 0; tix < ntiles; tix++) {
        int s0 = tix * 64;
        if (tix + 1 < ntiles) { asm volatile("cp.async.wait_group 1;"); }
        else                  { asm volatile("cp.async.wait_group 0;"); }
        __syncthreads();
        if (tix + 2 < ntiles) issue(tix + 2, (tix + 2) % 3);

        if (s0 <= rowbase + 15) {
            uint32_t kvB = su + (uint32_t)(tix % 3) * ASTG * 4;

            float sacc[8][4];
            #pragma unroll
            for (int nt = 0; nt < 8; nt++)
                #pragma unroll
                for (int e = 0; e < 4; e++) sacc[nt][e] = 0.f;

            #pragma unroll
            for (int ks = 0; ks < 4; ks++) {
                #pragma unroll
                for (int p = 0; p < 4; p++) {
                    uint32_t bb = kvB + (uint32_t)(p * 16 * ASV * 4) + ks * 32 + b_loff;
                    uint32_t kf[4];
                    ldsm4(kf, bb);
                    mma16816(sacc[2*p],   qh[ks], kf[0], kf[1]);
                    mma16816(sacc[2*p+1], qh[ks], kf[2], kf[3]);
                    mma16816(sacc[2*p],   ql[ks], kf[0], kf[1]);
                    mma16816(sacc[2*p+1], ql[ks], kf[2], kf[3]);
                }
            }

            if (s0 + 63 > rowbase) {
                int rA = rowbase + qr, rB = rA + 8;
                #pragma unroll
                for (int nt = 0; nt < 8; nt++) {
                    int c0 = s0 + nt * 8 + qc * 2;
                    if (c0 > rA)     sacc[nt][0] = -1e30f;
                    if (c0 + 1 > rA) sacc[nt][1] = -1e30f;
                    if (c0 > rB)     sacc[nt][2] = -1e30f;
                    if (c0 + 1 > rB) sacc[nt][3] = -1e30f;
                }
            }

            const float C1 = 0.125f * 1.44269504f;
            #pragma unroll
            for (int nt = 0; nt < 8; nt++) {
                float p0 = fexp2(sacc[nt][0] * C1);
                float p1 = fexp2(sacc[nt][1] * C1);
                float p2 = fexp2(sacc[nt][2] * C1);
                float p3 = fexp2(sacc[nt][3] * C1);
                sacc[nt][0] = p0; sacc[nt][1] = p1;
                sacc[nt][2] = p2; sacc[nt][3] = p3;
                lr[0] += p0 + p1;
                lr[1] += p2 + p3;
            }

            // ---- P -> fp16 hi/lo A-fragments ----
            uint32_t ph[4][4], pl[4][4];
            #pragma unroll
            for (int kk = 0; kk < 4; kk++) {
                float a0 = sacc[2*kk][0],   a1 = sacc[2*kk][1];
                float a2 = sacc[2*kk][2],   a3 = sacc[2*kk][3];
                float b0 = sacc[2*kk+1][0], b1 = sacc[2*kk+1][1];
                float b2 = sacc[2*kk+1][2], b3 = sacc[2*kk+1][3];
                ph[kk][0] = packh(a0, a1); ph[kk][1] = packh(a2, a3);
                ph[kk][2] = packh(b0, b1); ph[kk][3] = packh(b2, b3);
                pl[kk][0] = packh(floh(a0), floh(a1)); pl[kk][1] = packh(floh(a2), floh(a3));
                pl[kk][2] = packh(floh(b0), floh(b1)); pl[kk][3] = packh(floh(b2), floh(b3));
            }

            // ---- O += P V ----
            uint32_t vbB = kvB + AARR * 4;
            #pragma unroll
            for (int kk = 0; kk < 4; kk++) {
                #pragma unroll
                for (int p = 0; p < 4; p++) {
                    uint32_t vb = vbB + (uint32_t)(p * 16 * ASV * 4) + kk * 32 + b_loff;
                    uint32_t vf[4];
                    ldsm4(vf, vb);
                    mma16816(oacc[2*p],   ph[kk], vf[0], vf[1]);
                    mma16816(oacc[2*p+1], ph[kk], vf[2], vf[3]);
                    mma16816(oacc[2*p],   pl[kk], vf[0], vf[1]);
                    mma16816(oacc[2*p+1], pl[kk], vf[2], vf[3]);
                }
            }
        }
    }

    lr[0] += __shfl_xor_sync(0xffffffffu, lr[0], 1);
    lr[0] += __shfl_xor_sync(0xffffffffu, lr[0], 2);
    lr[1] += __shfl_xor_sync(0xffffffffu, lr[1], 1);
    lr[1] += __shfl_xor_sync(0xffffffffu, lr[1], 2);

    float ivA = 1.0f / lr[0], ivB = 1.0f / lr[1];
    int b = bh >> 4, h = bh & 15;
    int rA = rowbase + qr, rB = rA + 8;
    #pragma unroll
    for (int nt = 0; nt < 8; nt++) {
        int d = nt * 8 + qc * 2;
        size_t iA = ((size_t)(b * SEQ + rA)) * DIMC + h * HD + d;
        size_t iB = ((size_t)(b * SEQ + rB)) * DIMC + h * HD + d;
        float o0 = oacc[nt][0] * ivA, o1 = oacc[nt][1] * ivA;
        float o2 = oacc[nt][2] * ivB, o3 = oacc[nt][3] * ivB;
        *(uint32_t*)(g_ahi + iA) = packh(o0, o1);
        *(uint32_t*)(g_alo + iA) = packh(floh(o0), floh(o1));
        *(uint32_t*)(g_ahi + iB) = packh(o2, o3);
        *(uint32_t*)(g_alo + iB) = packh(floh(o2), floh(o3));
    }
}

// ---------------- launch ----------------
extern "C" void kernel_launch(void* const* d_in, const int* in_sizes, int n_in,
                              void* d_out, int out_size)
{
    const float* query = (const float*)d_in[0];
    const float* key   = (const float*)d_in[1];
    const float* value = (const float*)d_in[2];
    const float* Wq = (const float*)d_in[3];
    const float* bq = (const float*)d_in[4];
    const float* Wk = (const float*)d_in[5];
    const float* bk = (const float*)d_in[6];
    const float* Wv = (const float*)d_in[7];
    const float* bv = (const float*)d_in[8];
    const float* Wo = (const float*)d_in[9];
    const float* bo = (const float*)d_in[10];
    float* out = (float*)d_out;

    cudaFuncSetAttribute(pgemm_kernel<0>, cudaFuncAttributeMaxDynamicSharedMemorySize, GSMEM_BYTES);
    cudaFuncSetAttribute(pgemm_kernel<1>, cudaFuncAttributeMaxDynamicSharedMemorySize, GSMEM_BYTES);
    cudaFuncSetAttribute(attn_kernel, cudaFuncAttributeMaxDynamicSharedMemorySize, ATT_SMEM_BYTES);

    int n4 = BT * DIMC / 4;

    rope_table_kernel<<<SEQ * 32 / 256, 256>>>();
    asplit3_kernel<<<dim3(n4 / 256, 3), 256>>>((const float4*)query,
                                               (const float4*)key,
                                               (const float4*)value);
    wsplit4_kernel<<<dim3(32, 32, 4), dim3(32, 8)>>>(Wq, Wk, Wv, Wo);

    pgemm_kernel<0><<<dim3(8, 64, 3), 256, GSMEM_BYTES>>>(bq, bk, bv, nullptr);

    vtrans_kernel<<<dim3(SEQ / 64, BATCH * NH), 256>>>();

    attn_kernel<<<dim3(SEQ / 128, BATCH * NH), 256, ATT_SMEM_BYTES>>>();

    pgemm_kernel<1><<<dim3(8, 64, 1), 256, GSMEM_BYTES>>>(bo, nullptr, nullptr, out);
}

// round 15
// speedup vs baseline: 1.6394x; 1.1664x over previous
#include <cuda_runtime.h>
#include <cuda_fp16.h>
#include <math.h>
#include <stdint.h>

#define DIMC 1024
#define NH 16
#define HD 64
#define BATCH 4
#define SEQ 2048
#define BT (BATCH*SEQ)
#define MK ((size_t)BT*DIMC)
#define BHD ((size_t)BATCH*NH*SEQ*HD)

// ---------------- scratch (allocation-free) ----------------
__device__ float g_v[BHD];
__device__ __half g_qhi[BHD], g_qlo[BHD];        // RoPE'd Q hi/lo
__device__ __half g_khi[BHD];                    // RoPE'd K (fp16)
__device__ __half g_vthi[BHD];                   // V^T (fp16)
__device__ __half g_ahi[3*MK];                   // GEMM A slots hi (0=q/att,1=k,2=v)
__device__ __half g_alo[3*MK];                   // GEMM A slots lo (QKV only)
__device__ __half g_whi[4*(size_t)DIMC*DIMC];    // W (fp16) slots q,k,v,o
__device__ float2 g_rope[SEQ*32];

// ---------------- PTX helpers ----------------
__device__ __forceinline__ uint32_t smem_u32(const void* p) {
    uint32_t a;
    asm("{ .reg .u64 t; cvta.to.shared.u64 t, %1; cvt.u32.u64 %0, t; }" : "=r"(a) : "l"(p));
    return a;
}
__device__ __forceinline__ void cpasync16(uint32_t saddr, const void* g) {
    asm volatile("cp.async.cg.shared.global [%0], [%1], 16;" :: "r"(saddr), "l"(g));
}
__device__ __forceinline__ void ldsm4(uint32_t* r, uint32_t addr) {
    asm volatile("ldmatrix.sync.aligned.m8n8.x4.shared.b16 {%0,%1,%2,%3}, [%4];"
                 : "=r"(r[0]), "=r"(r[1]), "=r"(r[2]), "=r"(r[3]) : "r"(addr));
}
__device__ __forceinline__ void mma16816(float* d, const uint32_t* a, uint32_t b0, uint32_t b1) {
    asm volatile("mma.sync.aligned.m16n8k16.row.col.f32.f16.f16.f32 "
                 "{%0,%1,%2,%3}, {%4,%5,%6,%7}, {%8,%9}, {%0,%1,%2,%3};"
                 : "+f"(d[0]), "+f"(d[1]), "+f"(d[2]), "+f"(d[3])
                 : "r"(a[0]), "r"(a[1]), "r"(a[2]), "r"(a[3]), "r"(b0), "r"(b1));
}
__device__ __forceinline__ uint32_t packh(float a, float b) {
    __half2 t = __floats2half2_rn(a, b);
    return *(uint32_t*)&t;
}
__device__ __forceinline__ float floh(float x) {
    return x - __half2float(__float2half_rn(x));
}
__device__ __forceinline__ float fexp2(float t) {
    t = fmaxf(t, -30.0f);
    float r = t + 12582912.0f;
    int n = __float_as_int(r) - 0x4B400000;
    float f = t - (r - 12582912.0f);
    float p = 1.3333558146e-3f;
    p = fmaf(p, f, 9.6181291077e-3f);
    p = fmaf(p, f, 5.5504108664e-2f);
    p = fmaf(p, f, 2.4022650696e-1f);
    p = fmaf(p, f, 6.9314718056e-1f);
    p = fmaf(p, f, 1.0f);
    return __int_as_float(__float_as_int(p) + (n << 23));
}

// ---------------- fused prep: rope table + QKV split + W transpose/convert ----------------
// 1D grid partition: [0,256) rope; [256, 256+24576) asplit (z = idx/8192);
// [24832, 24832+4096) wsplit (z = idx/1024).
#define PREP_BLOCKS (256 + 3*8192 + 4*1024)

__global__ __launch_bounds__(256) void prep_kernel(const float4* __restrict__ q,
                                                   const float4* __restrict__ k,
                                                   const float4* __restrict__ v,
                                                   const float* __restrict__ Wq,
                                                   const float* __restrict__ Wk,
                                                   const float* __restrict__ Wv,
                                                   const float* __restrict__ Wo)
{
    __shared__ float tile[32][33];
    int bid = blockIdx.x, tid = threadIdx.x;

    if (bid < 256) {                       // rope table
        int idx = bid * 256 + tid;
        int t = idx >> 5, f = idx & 31;
        double invf = 1.0 / pow(10000.0, (double)(2 * f) / 64.0);
        float ang = (float)t * (float)invf;
        g_rope[idx] = make_float2((float)cos((double)ang), (float)sin((double)ang));
    } else if (bid < 256 + 3 * 8192) {     // A-side split (fp16 hi/lo)
        int r = bid - 256;
        int z = r >> 13;
        const float4* src = (z == 0) ? q : (z == 1) ? k : v;
        size_t i = (size_t)(r & 8191) * 256 + tid;
        float4 val = src[i];
        float vv[4] = {val.x, val.y, val.z, val.w};
        __half h[4], l[4];
        #pragma unroll
        for (int j = 0; j < 4; j++) {
            h[j] = __float2half_rn(vv[j]);
            l[j] = __float2half_rn(vv[j] - __half2float(h[j]));
        }
        size_t o = z * MK + 4 * i;
        *(uint2*)(g_ahi + o) = *(uint2*)h;
        *(uint2*)(g_alo + o) = *(uint2*)l;
    } else {                               // W transpose + fp16 convert
        int r = bid - (256 + 3 * 8192);
        int z = r >> 10;
        int rem = r & 1023;
        const float* W = (z == 0) ? Wq : (z == 1) ? Wk : (z == 2) ? Wv : Wo;
        size_t wof = (size_t)z * DIMC * DIMC;
        int n0 = (rem & 31) * 32, k0 = (rem >> 5) * 32;
        int x = tid & 31, y0 = tid >> 5;
        for (int j = y0; j < 32; j += 8)
            tile[j][x] = W[(size_t)(k0 + j) * DIMC + n0 + x];
        __syncthreads();
        for (int j = y0; j < 32; j += 8)
            g_whi[wof + (size_t)(n0 + j) * DIMC + k0 + x] = __float2half_rn(tile[x][j]);
    }
}

// V [B,H,S,D] fp32 -> V^T [B,H,D,S] fp16
__global__ __launch_bounds__(256) void vtrans_kernel() {
    __shared__ float tile[64][65];
    int s0 = blockIdx.x * 64;
    int bh = blockIdx.y;
    const float* Vb = g_v + (size_t)bh * SEQ * HD;
    int tid = threadIdx.x;
    #pragma unroll
    for (int j = 0; j < 4; j++) {
        int idx = tid + j * 256;
        int r = idx >> 4, c4 = (idx & 15) << 2;
        float4 v = *(const float4*)(Vb + (size_t)(s0 + r) * HD + c4);
        tile[c4 + 0][r] = v.x; tile[c4 + 1][r] = v.y;
        tile[c4 + 2][r] = v.z; tile[c4 + 3][r] = v.w;
    }
    __syncthreads();
    size_t ob = (size_t)bh * HD * SEQ + s0;
    #pragma unroll
    for (int j = 0; j < 8; j++) {
        int u = tid + j * 256;
        int d = u >> 5, sp = u & 31;
        *(uint32_t*)(g_vthi + ob + (size_t)d * SEQ + 2 * sp) =
            packh(tile[d][2 * sp], tile[d][2 * sp + 1]);
    }
}

// ---------------- 3-stage cp.async fp16 GEMM ----------------
// MODE 0 (QKV): C = (Ah+Al)*W, arrays/stage {Ahi, Alo, W}, 2 MMA passes.
// MODE 1 (out): C = Ah*W,      arrays/stage {Ahi, W},      1 MMA pass.
#define ROW_B 64
#define ARR_B (128*ROW_B)            // 8192 B

template<int MODE>
__global__ __launch_bounds__(256, 2) void pgemm_kernel(const float* __restrict__ b0p,
                                                       const float* __restrict__ b1p,
                                                       const float* __restrict__ b2p,
                                                       float* __restrict__ outp)
{
    constexpr int NARR = (MODE == 0) ? 3 : 2;
    constexpr int WARR = (MODE == 0) ? 2 : 1;    // W array index
    constexpr uint32_t STG = NARR * ARR_B;

    extern __shared__ uint32_t smu[];
    const uint32_t su = smem_u32(smu);

    const int tid  = threadIdx.x;
    const int lane = tid & 31;
    const int wid  = tid >> 5;
    const int wm = wid & 1;
    const int wn = wid >> 1;
    const int m0 = blockIdx.y << 7, n0 = blockIdx.x << 7;
    const int z = (MODE == 0) ? blockIdx.z : 3;

    const __half* ahi = g_ahi + ((MODE == 0) ? (size_t)z * MK : 0) + (size_t)m0 * DIMC;
    const __half* alo = g_alo + ((MODE == 0) ? (size_t)z * MK : 0) + (size_t)m0 * DIMC;
    const __half* whi = g_whi + (size_t)z * DIMC * DIMC + (size_t)n0 * DIMC;
    const float* bias = (MODE == 1) ? b0p : (z == 0) ? b0p : (z == 1) ? b1p : b2p;

    float acc[4][4][4];
    #pragma unroll
    for (int i = 0; i < 4; i++)
        #pragma unroll
        for (int j = 0; j < 4; j++)
            #pragma unroll
            for (int r = 0; r < 4; r++) acc[i][j][r] = 0.f;

    const int a_row = (lane & 7) + 8 * ((lane >> 3) & 1);
    const int a_cs  = (lane >> 4) & 1;
    const int b_row = (lane & 7) + 8 * ((lane >> 4) & 1);
    const int b_cs  = (lane >> 3) & 1;
    const int a_sw = (a_row >> 1) & 3, b_sw = (b_row >> 1) & 3;
    uint32_t a_off[2], b_off[2];
    #pragma unroll
    for (int ks2 = 0; ks2 < 2; ks2++) {
        a_off[ks2] = (uint32_t)(a_row * ROW_B + (((ks2 << 1) | a_cs) ^ a_sw) * 16);
        b_off[ks2] = (uint32_t)(b_row * ROW_B + (((ks2 << 1) | b_cs) ^ b_sw) * 16);
    }

    const int l_row = tid >> 1;
    const int l_cb  = (tid & 1) << 1;
    const int l_sw  = (l_row >> 1) & 3;

    auto issue = [&](int c, int buf) {
        int k0 = c << 5;
        uint32_t base = su + (uint32_t)buf * STG;
        #pragma unroll
        for (int j = 0; j < 2; j++) {
            int ch = l_cb + j;
            size_t g = (size_t)l_row * DIMC + k0 + ch * 8;
            uint32_t so = (uint32_t)(l_row * ROW_B + (ch ^ l_sw) * 16);
            cpasync16(base + 0 * ARR_B + so, ahi + g);
            if (MODE == 0) cpasync16(base + 1 * ARR_B + so, alo + g);
            cpasync16(base + WARR * ARR_B + so, whi + g);
        }
        asm volatile("cp.async.commit_group;");
    };

    issue(0, 0);
    issue(1, 1);
    for (int c = 0; c < 32; c++) {
        if (c < 31) { asm volatile("cp.async.wait_group 1;"); }
        else        { asm volatile("cp.async.wait_group 0;"); }
        __syncthreads();
        if (c + 2 < 32) issue(c + 2, (c + 2) % 3);

        uint32_t sb = su + (uint32_t)(c % 3) * STG;

        #pragma unroll
        for (int ks2 = 0; ks2 < 2; ks2++) {
            uint32_t ah[4][4], al[4][4], bh[2][4];
            #pragma unroll
            for (int mt = 0; mt < 4; mt++) {
                uint32_t ab = sb + (uint32_t)((wm * 64 + mt * 16) * ROW_B) + a_off[ks2];
                ldsm4(ah[mt], ab);
                if (MODE == 0) ldsm4(al[mt], ab + ARR_B);
            }
            #pragma unroll
            for (int p = 0; p < 2; p++) {
                uint32_t bb = sb + WARR * ARR_B
                            + (uint32_t)((wn * 32 + p * 16) * ROW_B) + b_off[ks2];
                ldsm4(bh[p], bb);
            }
            #pragma unroll
            for (int mt = 0; mt < 4; mt++)
                #pragma unroll
                for (int nt = 0; nt < 4; nt++) {
                    int p = nt >> 1, ix = (nt & 1) * 2;
                    mma16816(acc[mt][nt], ah[mt], bh[p][ix], bh[p][ix + 1]);
                }
            if (MODE == 0) {
                #pragma unroll
                for (int mt = 0; mt < 4; mt++)
                    #pragma unroll
                    for (int nt = 0; nt < 4; nt++) {
                        int p = nt >> 1, ix = (nt & 1) * 2;
                        mma16816(acc[mt][nt], al[mt], bh[p][ix], bh[p][ix + 1]);
                    }
            }
        }
    }

    const int quad = lane >> 2, tc = lane & 3;
    #pragma unroll
    for (int mt = 0; mt < 4; mt++) {
        #pragma unroll
        for (int nt = 0; nt < 4; nt++) {
            #pragma unroll
            for (int half = 0; half < 2; half++) {
                int m = m0 + wm * 64 + mt * 16 + quad + half * 8;
                int n = n0 + wn * 32 + nt * 8 + tc * 2;
                float v0 = acc[mt][nt][half * 2]     + bias[n];
                float v1 = acc[mt][nt][half * 2 + 1] + bias[n + 1];
                if (MODE == 0) {
                    int b = m >> 11, t = m & (SEQ - 1);
                    int h = n >> 6, d = n & 63;
                    size_t base = ((size_t)(b * NH + h) * SEQ + t) * HD + d;
                    if (z == 2) {
                        g_v[base]     = v0;
                        g_v[base + 1] = v1;
                    } else {
                        float2 cs = g_rope[t * 32 + (d >> 1)];
                        float oe = v0 * cs.x - v1 * cs.y;
                        float oo = v0 * cs.y + v1 * cs.x;
                        if (z == 0) {
                            *(uint32_t*)(g_qhi + base) = packh(oe, oo);
                            *(uint32_t*)(g_qlo + base) = packh(floh(oe), floh(oo));
                        } else {
                            *(uint32_t*)(g_khi + base) = packh(oe, oo);
                        }
                    }
                } else {
                    size_t base = (size_t)m * DIMC + n;
                    outp[base]     = v0;
                    outp[base + 1] = v1;
                }
            }
        }
    }
}
#define GSMEM0 (3*3*ARR_B)   // 73728
#define GSMEM1 (3*2*ARR_B)   // 49152

// ---------------- attention: fp16; Q hi/lo, single-fp16 K/V/P ----------------
#define ASV 36
#define AARR (64*ASV)
#define ASTG (2*AARR)
#define ATT_SMEM_BYTES (3*ASTG*4)   // 55296

__global__ __launch_bounds__(256, 2) void attn_kernel()
{
    extern __shared__ uint32_t smu[];
    const uint32_t su = smem_u32(smu);

    const int tid  = threadIdx.x;
    const int lane = tid & 31;
    const int wid  = tid >> 5;
    const int bh   = blockIdx.y;
    const int m0   = ((int)gridDim.x - 1 - (int)blockIdx.x) * 128;

    const size_t bhb = (size_t)bh * SEQ * HD;
    const __half* Khi = g_khi + bhb;
    const __half* Vthi = g_vthi + bhb;

    const uint32_t a_loff = (uint32_t)(((lane & 7) + 8 * ((lane >> 3) & 1)) * ASV * 4
                                       + ((lane >> 4) & 1) * 16);
    const uint32_t b_loff = (uint32_t)(((lane & 7) + 8 * ((lane >> 4) & 1)) * ASV * 4
                                       + ((lane >> 3) & 1) * 16);

    {
        const __half* Qhi = g_qhi + bhb + (size_t)m0 * HD;
        const __half* Qlo = g_qlo + bhb + (size_t)m0 * HD;
        #pragma unroll
        for (int j = 0; j < 4; j++) {
            int idx = tid + j * 256;
            int row = idx >> 3, seg = idx & 7;
            size_t g = (size_t)row * HD + seg * 8;
            int o = row * ASV + seg * 4;
            *(uint4*)(smu + o)        = *(const uint4*)(Qhi + g);
            *(uint4*)(smu + 4608 + o) = *(const uint4*)(Qlo + g);
        }
    }
    __syncthreads();
    uint32_t qh[4][4], ql[4][4];
    #pragma unroll
    for (int ks = 0; ks < 4; ks++) {
        uint32_t ab = su + (uint32_t)(wid * 16 * ASV * 4) + ks * 32 + a_loff;
        ldsm4(qh[ks], ab);
        ldsm4(ql[ks], ab + 4608 * 4);
    }
    __syncthreads();

    float oacc[8][4];
    #pragma unroll
    for (int nt = 0; nt < 8; nt++)
        #pragma unroll
        for (int e = 0; e < 4; e++) oacc[nt][e] = 0.f;
    float lr[2] = {0.f, 0.f};

    const int qr = lane >> 2, qc = lane & 3;
    const int rowbase = m0 + wid * 16;
    const int ntiles = m0 / 64 + 2;

    const int l_row = tid >> 2, l_seg = tid & 3;

    auto issue = [&](int tix, int buf) {
        int s0 = tix * 64;
        uint32_t base = su + (uint32_t)buf * ASTG * 4;
        #pragma unroll
        for (int ss = 0; ss < 2; ss++) {
            int seg = l_seg + ss * 4;
            uint32_t so = (uint32_t)(l_row * ASV + seg * 4) * 4;
            size_t gk = (size_t)(s0 + l_row) * HD + seg * 8;
            size_t gv = (size_t)l_row * SEQ + s0 + seg * 8;
            cpasync16(base + 0 * AARR * 4 + so, Khi + gk);
            cpasync16(base + 1 * AARR * 4 + so, Vthi + gv);
        }
        asm volatile("cp.async.commit_group;");
    };

    issue(0, 0);
    issue(1, 1);
    for (int tix = 0; tix < ntiles; tix++) {
        int s0 = tix * 64;
        if (tix + 1 < ntiles) { asm volatile("cp.async.wait_group 1;"); }
        else                  { asm volatile("cp.async.wait_group 0;"); }
        __syncthreads();
        if (tix + 2 < ntiles) issue(tix + 2, (tix + 2) % 3);

        if (s0 <= rowbase + 15) {
            uint32_t kvB = su + (uint32_t)(tix % 3) * ASTG * 4;

            float sacc[8][4];
            #pragma unroll
            for (int nt = 0; nt < 8; nt++)
                #pragma unroll
                for (int e = 0; e < 4; e++) sacc[nt][e] = 0.f;

            #pragma unroll
            for (int ks = 0; ks < 4; ks++) {
                #pragma unroll
                for (int p = 0; p < 4; p++) {
                    uint32_t bb = kvB + (uint32_t)(p * 16 * ASV * 4) + ks * 32 + b_loff;
                    uint32_t kf[4];
                    ldsm4(kf, bb);
                    mma16816(sacc[2*p],   qh[ks], kf[0], kf[1]);
                    mma16816(sacc[2*p+1], qh[ks], kf[2], kf[3]);
                    mma16816(sacc[2*p],   ql[ks], kf[0], kf[1]);
                    mma16816(sacc[2*p+1], ql[ks], kf[2], kf[3]);
                }
            }

            if (s0 + 63 > rowbase) {
                int rA = rowbase + qr, rB = rA + 8;
                #pragma unroll
                for (int nt = 0; nt < 8; nt++) {
                    int c0 = s0 + nt * 8 + qc * 2;
                    if (c0 > rA)     sacc[nt][0] = -1e30f;
                    if (c0 + 1 > rA) sacc[nt][1] = -1e30f;
                    if (c0 > rB)     sacc[nt][2] = -1e30f;
                    if (c0 + 1 > rB) sacc[nt][3] = -1e30f;
                }
            }

            const float C1 = 0.125f * 1.44269504f;
            #pragma unroll
            for (int nt = 0; nt < 8; nt++) {
                float p0 = fexp2(sacc[nt][0] * C1);
                float p1 = fexp2(sacc[nt][1] * C1);
                float p2 = fexp2(sacc[nt][2] * C1);
                float p3 = fexp2(sacc[nt][3] * C1);
                sacc[nt][0] = p0; sacc[nt][1] = p1;
                sacc[nt][2] = p2; sacc[nt][3] = p3;
                lr[0] += p0 + p1;
                lr[1] += p2 + p3;
            }

            // ---- P -> single fp16 A-fragments ----
            uint32_t ph[4][4];
            #pragma unroll
            for (int kk = 0; kk < 4; kk++) {
                ph[kk][0] = packh(sacc[2*kk][0],   sacc[2*kk][1]);
                ph[kk][1] = packh(sacc[2*kk][2],   sacc[2*kk][3]);
                ph[kk][2] = packh(sacc[2*kk+1][0], sacc[2*kk+1][1]);
                ph[kk][3] = packh(sacc[2*kk+1][2], sacc[2*kk+1][3]);
            }

            // ---- O += P V (single-term) ----
            uint32_t vbB = kvB + AARR * 4;
            #pragma unroll
            for (int kk = 0; kk < 4; kk++) {
                #pragma unroll
                for (int p = 0; p < 4; p++) {
                    uint32_t vb = vbB + (uint32_t)(p * 16 * ASV * 4) + kk * 32 + b_loff;
                    uint32_t vf[4];
                    ldsm4(vf, vb);
                    mma16816(oacc[2*p],   ph[kk], vf[0], vf[1]);
                    mma16816(oacc[2*p+1], ph[kk], vf[2], vf[3]);
                }
            }
        }
    }

    lr[0] += __shfl_xor_sync(0xffffffffu, lr[0], 1);
    lr[0] += __shfl_xor_sync(0xffffffffu, lr[0], 2);
    lr[1] += __shfl_xor_sync(0xffffffffu, lr[1], 1);
    lr[1] += __shfl_xor_sync(0xffffffffu, lr[1], 2);

    float ivA = 1.0f / lr[0], ivB = 1.0f / lr[1];
    int b = bh >> 4, h = bh & 15;
    int rA = rowbase + qr, rB = rA + 8;
    #pragma unroll
    for (int nt = 0; nt < 8; nt++) {
        int d = nt * 8 + qc * 2;
        size_t iA = ((size_t)(b * SEQ + rA)) * DIMC + h * HD + d;
        size_t iB = ((size_t)(b * SEQ + rB)) * DIMC + h * HD + d;
        *(uint32_t*)(g_ahi + iA) = packh(oacc[nt][0] * ivA, oacc[nt][1] * ivA);
        *(uint32_t*)(g_ahi + iB) = packh(oacc[nt][2] * ivB, oacc[nt][3] * ivB);
    }
}

// ---------------- launch ----------------
extern "C" void kernel_launch(void* const* d_in, const int* in_sizes, int n_in,
                              void* d_out, int out_size)
{
    const float* query = (const float*)d_in[0];
    const float* key   = (const float*)d_in[1];
    const float* value = (const float*)d_in[2];
    const float* Wq = (const float*)d_in[3];
    const float* bq = (const float*)d_in[4];
    const float* Wk = (const float*)d_in[5];
    const float* bk = (const float*)d_in[6];
    const float* Wv = (const float*)d_in[7];
    const float* bv = (const float*)d_in[8];
    const float* Wo = (const float*)d_in[9];
    const float* bo = (const float*)d_in[10];
    float* out = (float*)d_out;

    cudaFuncSetAttribute(pgemm_kernel<0>, cudaFuncAttributeMaxDynamicSharedMemorySize, GSMEM0);
    cudaFuncSetAttribute(pgemm_kernel<1>, cudaFuncAttributeMaxDynamicSharedMemorySize, GSMEM1);
    cudaFuncSetAttribute(attn_kernel, cudaFuncAttributeMaxDynamicSharedMemorySize, ATT_SMEM_BYTES);

    prep_kernel<<<PREP_BLOCKS, 256>>>((const float4*)query, (const float4*)key,
                                      (const float4*)value, Wq, Wk, Wv, Wo);

    pgemm_kernel<0><<<dim3(8, 64, 3), 256, GSMEM0>>>(bq, bk, bv, nullptr);

    vtrans_kernel<<<dim3(SEQ / 64, BATCH * NH), 256>>>();

    attn_kernel<<<dim3(SEQ / 128, BATCH * NH), 256, ATT_SMEM_BYTES>>>();

    pgemm_kernel<1><<<dim3(8, 64, 1), 256, GSMEM1>>>(bo, nullptr, nullptr, out);
}

// round 16
// speedup vs baseline: 1.9039x; 1.1614x over previous
#include <cuda_runtime.h>
#include <cuda_fp16.h>
#include <math.h>
#include <stdint.h>

#define DIMC 1024
#define NH 16
#define HD 64
#define BATCH 4
#define SEQ 2048
#define BT (BATCH*SEQ)
#define MK ((size_t)BT*DIMC)
#define BHD ((size_t)BATCH*NH*SEQ*HD)

// ---------------- scratch (allocation-free) ----------------
__device__ __half g_qhi[BHD];                    // RoPE'd Q (fp16)
__device__ __half g_khi[BHD];                    // RoPE'd K (fp16)
__device__ __half g_vthi[BHD];                   // V^T (fp16) [B,H,D,S]
__device__ __half g_ahi[3*MK];                   // GEMM A slots hi (0=q/att,1=k,2=v)
__device__ __half g_alo[3*MK];                   // GEMM A slots lo (used z=0,1)
__device__ __half g_whi[4*(size_t)DIMC*DIMC];    // W (fp16) slots q,k,v,o
__device__ float2 g_rope[SEQ*32];

// ---------------- PTX helpers ----------------
__device__ __forceinline__ uint32_t smem_u32(const void* p) {
    uint32_t a;
    asm("{ .reg .u64 t; cvta.to.shared.u64 t, %1; cvt.u32.u64 %0, t; }" : "=r"(a) : "l"(p));
    return a;
}
__device__ __forceinline__ void cpasync16(uint32_t saddr, const void* g) {
    asm volatile("cp.async.cg.shared.global [%0], [%1], 16;" :: "r"(saddr), "l"(g));
}
__device__ __forceinline__ void ldsm4(uint32_t* r, uint32_t addr) {
    asm volatile("ldmatrix.sync.aligned.m8n8.x4.shared.b16 {%0,%1,%2,%3}, [%4];"
                 : "=r"(r[0]), "=r"(r[1]), "=r"(r[2]), "=r"(r[3]) : "r"(addr));
}
__device__ __forceinline__ void mma16816(float* d, const uint32_t* a, uint32_t b0, uint32_t b1) {
    asm volatile("mma.sync.aligned.m16n8k16.row.col.f32.f16.f16.f32 "
                 "{%0,%1,%2,%3}, {%4,%5,%6,%7}, {%8,%9}, {%0,%1,%2,%3};"
                 : "+f"(d[0]), "+f"(d[1]), "+f"(d[2]), "+f"(d[3])
                 : "r"(a[0]), "r"(a[1]), "r"(a[2]), "r"(a[3]), "r"(b0), "r"(b1));
}
__device__ __forceinline__ uint32_t packh(float a, float b) {
    __half2 t = __floats2half2_rn(a, b);
    return *(uint32_t*)&t;
}
__device__ __forceinline__ float floh(float x) {
    return x - __half2float(__float2half_rn(x));
}
__device__ __forceinline__ float fexp2(float t) {
    t = fmaxf(t, -30.0f);
    float r = t + 12582912.0f;
    int n = __float_as_int(r) - 0x4B400000;
    float f = t - (r - 12582912.0f);
    float p = 1.3333558146e-3f;
    p = fmaf(p, f, 9.6181291077e-3f);
    p = fmaf(p, f, 5.5504108664e-2f);
    p = fmaf(p, f, 2.4022650696e-1f);
    p = fmaf(p, f, 6.9314718056e-1f);
    p = fmaf(p, f, 1.0f);
    return __int_as_float(__float_as_int(p) + (n << 23));
}

// ---------------- fused prep: rope table + QKV split + W transpose/convert ----------------
#define PREP_BLOCKS (256 + 3*8192 + 4*1024)

__global__ __launch_bounds__(256) void prep_kernel(const float4* __restrict__ q,
                                                   const float4* __restrict__ k,
                                                   const float4* __restrict__ v,
                                                   const float* __restrict__ Wq,
                                                   const float* __restrict__ Wk,
                                                   const float* __restrict__ Wv,
                                                   const float* __restrict__ Wo)
{
    __shared__ float tile[32][33];
    int bid = blockIdx.x, tid = threadIdx.x;

    if (bid < 256) {                       // rope table
        int idx = bid * 256 + tid;
        int t = idx >> 5, f = idx & 31;
        double invf = 1.0 / pow(10000.0, (double)(2 * f) / 64.0);
        float ang = (float)t * (float)invf;
        g_rope[idx] = make_float2((float)cos((double)ang), (float)sin((double)ang));
    } else if (bid < 256 + 3 * 8192) {     // A-side split
        int r = bid - 256;
        int z = r >> 13;
        const float4* src = (z == 0) ? q : (z == 1) ? k : v;
        size_t i = (size_t)(r & 8191) * 256 + tid;
        float4 val = src[i];
        float vv[4] = {val.x, val.y, val.z, val.w};
        __half h[4], l[4];
        #pragma unroll
        for (int j = 0; j < 4; j++) {
            h[j] = __float2half_rn(vv[j]);
            l[j] = __float2half_rn(vv[j] - __half2float(h[j]));
        }
        size_t o = z * MK + 4 * i;
        *(uint2*)(g_ahi + o) = *(uint2*)h;
        if (z != 2) *(uint2*)(g_alo + o) = *(uint2*)l;   // V path is single-term
    } else {                               // W transpose + fp16 convert
        int r = bid - (256 + 3 * 8192);
        int z = r >> 10;
        int rem = r & 1023;
        const float* W = (z == 0) ? Wq : (z == 1) ? Wk : (z == 2) ? Wv : Wo;
        size_t wof = (size_t)z * DIMC * DIMC;
        int n0 = (rem & 31) * 32, k0 = (rem >> 5) * 32;
        int x = tid & 31, y0 = tid >> 5;
        for (int j = y0; j < 32; j += 8)
            tile[j][x] = W[(size_t)(k0 + j) * DIMC + n0 + x];
        __syncthreads();
        for (int j = y0; j < 32; j += 8)
            g_whi[wof + (size_t)(n0 + j) * DIMC + k0 + x] = __float2half_rn(tile[x][j]);
    }
}

// ---------------- 3-stage cp.async fp16 GEMM ----------------
// MODE 0 (QKV): z=0,1 -> C=(Ah+Al)*W; z=2 -> C=Ah*W (V path, epilogue writes V^T).
// MODE 1 (out): C = Ah*W.
#define ROW_B 64
#define ARR_B (128*ROW_B)            // 8192 B

template<int MODE>
__global__ __launch_bounds__(256, 2) void pgemm_kernel(const float* __restrict__ b0p,
                                                       const float* __restrict__ b1p,
                                                       const float* __restrict__ b2p,
                                                       float* __restrict__ outp)
{
    constexpr int NARR = (MODE == 0) ? 3 : 2;
    constexpr int WARR = (MODE == 0) ? 2 : 1;
    constexpr uint32_t STG = NARR * ARR_B;

    extern __shared__ uint32_t smu[];
    const uint32_t su = smem_u32(smu);

    const int tid  = threadIdx.x;
    const int lane = tid & 31;
    const int wid  = tid >> 5;
    const int wm = wid & 1;
    const int wn = wid >> 1;
    const int m0 = blockIdx.y << 7, n0 = blockIdx.x << 7;
    const int z = (MODE == 0) ? blockIdx.z : 3;
    const bool uselo = (MODE == 0) && (z != 2);

    const __half* ahi = g_ahi + ((MODE == 0) ? (size_t)z * MK : 0) + (size_t)m0 * DIMC;
    const __half* alo = g_alo + ((MODE == 0) ? (size_t)z * MK : 0) + (size_t)m0 * DIMC;
    const __half* whi = g_whi + (size_t)z * DIMC * DIMC + (size_t)n0 * DIMC;
    const float* bias = (MODE == 1) ? b0p : (z == 0) ? b0p : (z == 1) ? b1p : b2p;

    float acc[4][4][4];
    #pragma unroll
    for (int i = 0; i < 4; i++)
        #pragma unroll
        for (int j = 0; j < 4; j++)
            #pragma unroll
            for (int r = 0; r < 4; r++) acc[i][j][r] = 0.f;

    const int a_row = (lane & 7) + 8 * ((lane >> 3) & 1);
    const int a_cs  = (lane >> 4) & 1;
    const int b_row = (lane & 7) + 8 * ((lane >> 4) & 1);
    const int b_cs  = (lane >> 3) & 1;
    const int a_sw = (a_row >> 1) & 3, b_sw = (b_row >> 1) & 3;
    uint32_t a_off[2], b_off[2];
    #pragma unroll
    for (int ks2 = 0; ks2 < 2; ks2++) {
        a_off[ks2] = (uint32_t)(a_row * ROW_B + (((ks2 << 1) | a_cs) ^ a_sw) * 16);
        b_off[ks2] = (uint32_t)(b_row * ROW_B + (((ks2 << 1) | b_cs) ^ b_sw) * 16);
    }

    const int l_row = tid >> 1;
    const int l_cb  = (tid & 1) << 1;
    const int l_sw  = (l_row >> 1) & 3;

    auto issue = [&](int c, int buf) {
        int k0 = c << 5;
        uint32_t base = su + (uint32_t)buf * STG;
        #pragma unroll
        for (int j = 0; j < 2; j++) {
            int ch = l_cb + j;
            size_t g = (size_t)l_row * DIMC + k0 + ch * 8;
            uint32_t so = (uint32_t)(l_row * ROW_B + (ch ^ l_sw) * 16);
            cpasync16(base + 0 * ARR_B + so, ahi + g);
            if (uselo) cpasync16(base + 1 * ARR_B + so, alo + g);
            cpasync16(base + WARR * ARR_B + so, whi + g);
        }
        asm volatile("cp.async.commit_group;");
    };

    issue(0, 0);
    issue(1, 1);
    for (int c = 0; c < 32; c++) {
        if (c < 31) { asm volatile("cp.async.wait_group 1;"); }
        else        { asm volatile("cp.async.wait_group 0;"); }
        __syncthreads();
        if (c + 2 < 32) issue(c + 2, (c + 2) % 3);

        uint32_t sb = su + (uint32_t)(c % 3) * STG;

        #pragma unroll
        for (int ks2 = 0; ks2 < 2; ks2++) {
            uint32_t ah[4][4], al[4][4], bh[2][4];
            #pragma unroll
            for (int mt = 0; mt < 4; mt++) {
                uint32_t ab = sb + (uint32_t)((wm * 64 + mt * 16) * ROW_B) + a_off[ks2];
                ldsm4(ah[mt], ab);
                if (uselo) ldsm4(al[mt], ab + ARR_B);
            }
            #pragma unroll
            for (int p = 0; p < 2; p++) {
                uint32_t bb = sb + WARR * ARR_B
                            + (uint32_t)((wn * 32 + p * 16) * ROW_B) + b_off[ks2];
                ldsm4(bh[p], bb);
            }
            #pragma unroll
            for (int mt = 0; mt < 4; mt++)
                #pragma unroll
                for (int nt = 0; nt < 4; nt++) {
                    int p = nt >> 1, ix = (nt & 1) * 2;
                    mma16816(acc[mt][nt], ah[mt], bh[p][ix], bh[p][ix + 1]);
                }
            if (uselo) {
                #pragma unroll
                for (int mt = 0; mt < 4; mt++)
                    #pragma unroll
                    for (int nt = 0; nt < 4; nt++) {
                        int p = nt >> 1, ix = (nt & 1) * 2;
                        mma16816(acc[mt][nt], al[mt], bh[p][ix], bh[p][ix + 1]);
                    }
            }
        }
    }

    const int quad = lane >> 2, tc = lane & 3;
    #pragma unroll
    for (int mt = 0; mt < 4; mt++) {
        #pragma unroll
        for (int nt = 0; nt < 4; nt++) {
            #pragma unroll
            for (int half = 0; half < 2; half++) {
                int m = m0 + wm * 64 + mt * 16 + quad + half * 8;
                int n = n0 + wn * 32 + nt * 8 + tc * 2;
                float v0 = acc[mt][nt][half * 2]     + bias[n];
                float v1 = acc[mt][nt][half * 2 + 1] + bias[n + 1];
                if (MODE == 0) {
                    int b = m >> 11, t = m & (SEQ - 1);
                    int h = n >> 6, d = n & 63;
                    if (z == 2) {
                        // write V^T fp16 directly: [B,H,D,S]
                        size_t vb = ((size_t)(b * NH + h) * HD + d) * SEQ + t;
                        g_vthi[vb]       = __float2half_rn(v0);
                        g_vthi[vb + SEQ] = __float2half_rn(v1);
                    } else {
                        float2 cs = g_rope[t * 32 + (d >> 1)];
                        float oe = v0 * cs.x - v1 * cs.y;
                        float oo = v0 * cs.y + v1 * cs.x;
                        size_t base = ((size_t)(b * NH + h) * SEQ + t) * HD + d;
                        if (z == 0) *(uint32_t*)(g_qhi + base) = packh(oe, oo);
                        else        *(uint32_t*)(g_khi + base) = packh(oe, oo);
                    }
                } else {
                    size_t base = (size_t)m * DIMC + n;
                    outp[base]     = v0;
                    outp[base + 1] = v1;
                }
            }
        }
    }
}
#define GSMEM0 (3*3*ARR_B)   // 73728
#define GSMEM1 (3*2*ARR_B)   // 49152

// ---------------- attention: single-fp16 Q/K/V/P ----------------
#define ASV 36
#define AARR (64*ASV)
#define ASTG (2*AARR)
#define ATT_SMEM_BYTES (3*ASTG*4)   // 55296

__global__ __launch_bounds__(256, 2) void attn_kernel()
{
    extern __shared__ uint32_t smu[];
    const uint32_t su = smem_u32(smu);

    const int tid  = threadIdx.x;
    const int lane = tid & 31;
    const int wid  = tid >> 5;
    const int bh   = blockIdx.y;
    const int m0   = ((int)gridDim.x - 1 - (int)blockIdx.x) * 128;

    const size_t bhb = (size_t)bh * SEQ * HD;
    const __half* Khi = g_khi + bhb;
    const __half* Vthi = g_vthi + bhb;

    const uint32_t a_loff = (uint32_t)(((lane & 7) + 8 * ((lane >> 3) & 1)) * ASV * 4
                                       + ((lane >> 4) & 1) * 16);
    const uint32_t b_loff = (uint32_t)(((lane & 7) + 8 * ((lane >> 4) & 1)) * ASV * 4
                                       + ((lane >> 3) & 1) * 16);

    // ---- prologue: stage Q tile (hi only), frags to regs ----
    {
        const __half* Qhi = g_qhi + bhb + (size_t)m0 * HD;
        #pragma unroll
        for (int j = 0; j < 4; j++) {
            int idx = tid + j * 256;
            int row = idx >> 3, seg = idx & 7;
            size_t g = (size_t)row * HD + seg * 8;
            *(uint4*)(smu + row * ASV + seg * 4) = *(const uint4*)(Qhi + g);
        }
    }
    __syncthreads();
    uint32_t qh[4][4];
    #pragma unroll
    for (int ks = 0; ks < 4; ks++) {
        uint32_t ab = su + (uint32_t)(wid * 16 * ASV * 4) + ks * 32 + a_loff;
        ldsm4(qh[ks], ab);
    }
    __syncthreads();

    float oacc[8][4];
    #pragma unroll
    for (int nt = 0; nt < 8; nt++)
        #pragma unroll
        for (int e = 0; e < 4; e++) oacc[nt][e] = 0.f;
    float lr[2] = {0.f, 0.f};

    const int qr = lane >> 2, qc = lane & 3;
    const int rowbase = m0 + wid * 16;
    const int ntiles = m0 / 64 + 2;

    const int l_row = tid >> 2, l_seg = tid & 3;

    auto issue = [&](int tix, int buf) {
        int s0 = tix * 64;
        uint32_t base = su + (uint32_t)buf * ASTG * 4;
        #pragma unroll
        for (int ss = 0; ss < 2; ss++) {
            int seg = l_seg + ss * 4;
            uint32_t so = (uint32_t)(l_row * ASV + seg * 4) * 4;
            size_t gk = (size_t)(s0 + l_row) * HD + seg * 8;
            size_t gv = (size_t)l_row * SEQ + s0 + seg * 8;
            cpasync16(base + 0 * AARR * 4 + so, Khi + gk);
            cpasync16(base + 1 * AARR * 4 + so, Vthi + gv);
        }
        asm volatile("cp.async.commit_group;");
    };

    issue(0, 0);
    issue(1, 1);
    for (int tix = 0; tix < ntiles; tix++) {
        int s0 = tix * 64;
        if (tix + 1 < ntiles) { asm volatile("cp.async.wait_group 1;"); }
        else                  { asm volatile("cp.async.wait_group 0;"); }
        __syncthreads();
        if (tix + 2 < ntiles) issue(tix + 2, (tix + 2) % 3);

        if (s0 <= rowbase + 15) {
            uint32_t kvB = su + (uint32_t)(tix % 3) * ASTG * 4;

            float sacc[8][4];
            #pragma unroll
            for (int nt = 0; nt < 8; nt++)
                #pragma unroll
                for (int e = 0; e < 4; e++) sacc[nt][e] = 0.f;

            #pragma unroll
            for (int ks = 0; ks < 4; ks++) {
                #pragma unroll
                for (int p = 0; p < 4; p++) {
                    uint32_t bb = kvB + (uint32_t)(p * 16 * ASV * 4) + ks * 32 + b_loff;
                    uint32_t kf[4];
                    ldsm4(kf, bb);
                    mma16816(sacc[2*p],   qh[ks], kf[0], kf[1]);
                    mma16816(sacc[2*p+1], qh[ks], kf[2], kf[3]);
                }
            }

            if (s0 + 63 > rowbase) {
                int rA = rowbase + qr, rB = rA + 8;
                #pragma unroll
                for (int nt = 0; nt < 8; nt++) {
                    int c0 = s0 + nt * 8 + qc * 2;
                    if (c0 > rA)     sacc[nt][0] = -1e30f;
                    if (c0 + 1 > rA) sacc[nt][1] = -1e30f;
                    if (c0 > rB)     sacc[nt][2] = -1e30f;
                    if (c0 + 1 > rB) sacc[nt][3] = -1e30f;
                }
            }

            const float C1 = 0.125f * 1.44269504f;
            #pragma unroll
            for (int nt = 0; nt < 8; nt++) {
                float p0 = fexp2(sacc[nt][0] * C1);
                float p1 = fexp2(sacc[nt][1] * C1);
                float p2 = fexp2(sacc[nt][2] * C1);
                float p3 = fexp2(sacc[nt][3] * C1);
                sacc[nt][0] = p0; sacc[nt][1] = p1;
                sacc[nt][2] = p2; sacc[nt][3] = p3;
                lr[0] += p0 + p1;
                lr[1] += p2 + p3;
            }

            uint32_t ph[4][4];
            #pragma unroll
            for (int kk = 0; kk < 4; kk++) {
                ph[kk][0] = packh(sacc[2*kk][0],   sacc[2*kk][1]);
                ph[kk][1] = packh(sacc[2*kk][2],   sacc[2*kk][3]);
                ph[kk][2] = packh(sacc[2*kk+1][0], sacc[2*kk+1][1]);
                ph[kk][3] = packh(sacc[2*kk+1][2], sacc[2*kk+1][3]);
            }

            uint32_t vbB = kvB + AARR * 4;
            #pragma unroll
            for (int kk = 0; kk < 4; kk++) {
                #pragma unroll
                for (int p = 0; p < 4; p++) {
                    uint32_t vb = vbB + (uint32_t)(p * 16 * ASV * 4) + kk * 32 + b_loff;
                    uint32_t vf[4];
                    ldsm4(vf, vb);
                    mma16816(oacc[2*p],   ph[kk], vf[0], vf[1]);
                    mma16816(oacc[2*p+1], ph[kk], vf[2], vf[3]);
                }
            }
        }
    }

    lr[0] += __shfl_xor_sync(0xffffffffu, lr[0], 1);
    lr[0] += __shfl_xor_sync(0xffffffffu, lr[0], 2);
    lr[1] += __shfl_xor_sync(0xffffffffu, lr[1], 1);
    lr[1] += __shfl_xor_sync(0xffffffffu, lr[1], 2);

    float ivA = 1.0f / lr[0], ivB = 1.0f / lr[1];
    int b = bh >> 4, h = bh & 15;
    int rA = rowbase + qr, rB = rA + 8;
    #pragma unroll
    for (int nt = 0; nt < 8; nt++) {
        int d = nt * 8 + qc * 2;
        size_t iA = ((size_t)(b * SEQ + rA)) * DIMC + h * HD + d;
        size_t iB = ((size_t)(b * SEQ + rB)) * DIMC + h * HD + d;
        *(uint32_t*)(g_ahi + iA) = packh(oacc[nt][0] * ivA, oacc[nt][1] * ivA);
        *(uint32_t*)(g_ahi + iB) = packh(oacc[nt][2] * ivB, oacc[nt][3] * ivB);
    }
}

// ---------------- launch ----------------
extern "C" void kernel_launch(void* const* d_in, const int* in_sizes, int n_in,
                              void* d_out, int out_size)
{
    const float* query = (const float*)d_in[0];
    const float* key   = (const float*)d_in[1];
    const float* value = (const float*)d_in[2];
    const float* Wq = (const float*)d_in[3];
    const float* bq = (const float*)d_in[4];
    const float* Wk = (const float*)d_in[5];
    const float* bk = (const float*)d_in[6];
    const float* Wv = (const float*)d_in[7];
    const float* bv = (const float*)d_in[8];
    const float* Wo = (const float*)d_in[9];
    const float* bo = (const float*)d_in[10];
    float* out = (float*)d_out;

    cudaFuncSetAttribute(pgemm_kernel<0>, cudaFuncAttributeMaxDynamicSharedMemorySize, GSMEM0);
    cudaFuncSetAttribute(pgemm_kernel<1>, cudaFuncAttributeMaxDynamicSharedMemorySize, GSMEM1);
    cudaFuncSetAttribute(attn_kernel, cudaFuncAttributeMaxDynamicSharedMemorySize, ATT_SMEM_BYTES);

    prep_kernel<<<PREP_BLOCKS, 256>>>((const float4*)query, (const float4*)key,
                                      (const float4*)value, Wq, Wk, Wv, Wo);

    pgemm_kernel<0><<<dim3(8, 64, 3), 256, GSMEM0>>>(bq, bk, bv, nullptr);

    attn_kernel<<<dim3(SEQ / 128, BATCH * NH), 256, ATT_SMEM_BYTES>>>();

    pgemm_kernel<1><<<dim3(8, 64, 1), 256, GSMEM1>>>(bo, nullptr, nullptr, out);
}

// round 17
// speedup vs baseline: 2.2108x; 1.1612x over previous
#include <cuda_runtime.h>
#include <cuda_fp16.h>
#include <math.h>
#include <stdint.h>

#define DIMC 1024
#define NH 16
#define HD 64
#define BATCH 4
#define SEQ 2048
#define BT (BATCH*SEQ)
#define MK ((size_t)BT*DIMC)
#define BHD ((size_t)BATCH*NH*SEQ*HD)

// ---------------- scratch (allocation-free) ----------------
__device__ __half g_qhi[BHD];                    // RoPE'd Q (fp16)
__device__ __half g_khi[BHD];                    // RoPE'd K (fp16)
__device__ __half g_vthi[BHD];                   // V^T (fp16) [B,H,D,S]
__device__ __half g_ahi[3*MK];                   // GEMM A slots (0=q/att,1=k,2=v)
__device__ __half g_whi[4*(size_t)DIMC*DIMC];    // W (fp16) slots q,k,v,o
__device__ float2 g_rope[SEQ*32];

// ---------------- PTX helpers ----------------
__device__ __forceinline__ uint32_t smem_u32(const void* p) {
    uint32_t a;
    asm("{ .reg .u64 t; cvta.to.shared.u64 t, %1; cvt.u32.u64 %0, t; }" : "=r"(a) : "l"(p));
    return a;
}
__device__ __forceinline__ void cpasync16(uint32_t saddr, const void* g) {
    asm volatile("cp.async.cg.shared.global [%0], [%1], 16;" :: "r"(saddr), "l"(g));
}
__device__ __forceinline__ void ldsm4(uint32_t* r, uint32_t addr) {
    asm volatile("ldmatrix.sync.aligned.m8n8.x4.shared.b16 {%0,%1,%2,%3}, [%4];"
                 : "=r"(r[0]), "=r"(r[1]), "=r"(r[2]), "=r"(r[3]) : "r"(addr));
}
__device__ __forceinline__ void mma16816(float* d, const uint32_t* a, uint32_t b0, uint32_t b1) {
    asm volatile("mma.sync.aligned.m16n8k16.row.col.f32.f16.f16.f32 "
                 "{%0,%1,%2,%3}, {%4,%5,%6,%7}, {%8,%9}, {%0,%1,%2,%3};"
                 : "+f"(d[0]), "+f"(d[1]), "+f"(d[2]), "+f"(d[3])
                 : "r"(a[0]), "r"(a[1]), "r"(a[2]), "r"(a[3]), "r"(b0), "r"(b1));
}
__device__ __forceinline__ uint32_t packh(float a, float b) {
    __half2 t = __floats2half2_rn(a, b);
    return *(uint32_t*)&t;
}
__device__ __forceinline__ float fexp2(float t) {
    t = fmaxf(t, -30.0f);
    float r = t + 12582912.0f;
    int n = __float_as_int(r) - 0x4B400000;
    float f = t - (r - 12582912.0f);
    float p = 1.3333558146e-3f;
    p = fmaf(p, f, 9.6181291077e-3f);
    p = fmaf(p, f, 5.5504108664e-2f);
    p = fmaf(p, f, 2.4022650696e-1f);
    p = fmaf(p, f, 6.9314718056e-1f);
    p = fmaf(p, f, 1.0f);
    return __int_as_float(__float_as_int(p) + (n << 23));
}

// ---------------- fused prep: rope table + QKV fp16 convert + W transpose/convert ----------------
#define PREP_BLOCKS (256 + 3*8192 + 4*1024)

__global__ __launch_bounds__(256) void prep_kernel(const float4* __restrict__ q,
                                                   const float4* __restrict__ k,
                                                   const float4* __restrict__ v,
                                                   const float* __restrict__ Wq,
                                                   const float* __restrict__ Wk,
                                                   const float* __restrict__ Wv,
                                                   const float* __restrict__ Wo)
{
    __shared__ float tile[32][33];
    int bid = blockIdx.x, tid = threadIdx.x;

    if (bid < 256) {                       // rope table
        int idx = bid * 256 + tid;
        int t = idx >> 5, f = idx & 31;
        double invf = 1.0 / pow(10000.0, (double)(2 * f) / 64.0);
        float ang = (float)t * (float)invf;
        g_rope[idx] = make_float2((float)cos((double)ang), (float)sin((double)ang));
    } else if (bid < 256 + 3 * 8192) {     // A-side fp16 convert
        int r = bid - 256;
        int z = r >> 13;
        const float4* src = (z == 0) ? q : (z == 1) ? k : v;
        size_t i = (size_t)(r & 8191) * 256 + tid;
        float4 val = src[i];
        __half h[4] = { __float2half_rn(val.x), __float2half_rn(val.y),
                        __float2half_rn(val.z), __float2half_rn(val.w) };
        *(uint2*)(g_ahi + z * MK + 4 * i) = *(uint2*)h;
    } else {                               // W transpose + fp16 convert
        int r = bid - (256 + 3 * 8192);
        int z = r >> 10;
        int rem = r & 1023;
        const float* W = (z == 0) ? Wq : (z == 1) ? Wk : (z == 2) ? Wv : Wo;
        size_t wof = (size_t)z * DIMC * DIMC;
        int n0 = (rem & 31) * 32, k0 = (rem >> 5) * 32;
        int x = tid & 31, y0 = tid >> 5;
        for (int j = y0; j < 32; j += 8)
            tile[j][x] = W[(size_t)(k0 + j) * DIMC + n0 + x];
        __syncthreads();
        for (int j = y0; j < 32; j += 8)
            g_whi[wof + (size_t)(n0 + j) * DIMC + k0 + x] = __float2half_rn(tile[x][j]);
    }
}

// ---------------- 3-stage cp.async fp16 GEMM (single-term everywhere) ----------------
// MODE 0 (QKV, z=blockIdx.z): epilogues — z=0 Q+RoPE, z=1 K+RoPE, z=2 V^T write.
// MODE 1 (out): writes outp.
#define ROW_B 64
#define ARR_B (128*ROW_B)            // 8192 B
#define STG (2*ARR_B)                // {A, W}
#define GSMEM_BYTES (3*STG)          // 49152

template<int MODE>
__global__ __launch_bounds__(256, 2) void pgemm_kernel(const float* __restrict__ b0p,
                                                       const float* __restrict__ b1p,
                                                       const float* __restrict__ b2p,
                                                       float* __restrict__ outp)
{
    extern __shared__ uint32_t smu[];
    const uint32_t su = smem_u32(smu);

    const int tid  = threadIdx.x;
    const int lane = tid & 31;
    const int wid  = tid >> 5;
    const int wm = wid & 1;
    const int wn = wid >> 1;
    const int m0 = blockIdx.y << 7, n0 = blockIdx.x << 7;
    const int z = (MODE == 0) ? blockIdx.z : 3;

    const __half* ahi = g_ahi + ((MODE == 0) ? (size_t)z * MK : 0) + (size_t)m0 * DIMC;
    const __half* whi = g_whi + (size_t)z * DIMC * DIMC + (size_t)n0 * DIMC;
    const float* bias = (MODE == 1) ? b0p : (z == 0) ? b0p : (z == 1) ? b1p : b2p;

    float acc[4][4][4];
    #pragma unroll
    for (int i = 0; i < 4; i++)
        #pragma unroll
        for (int j = 0; j < 4; j++)
            #pragma unroll
            for (int r = 0; r < 4; r++) acc[i][j][r] = 0.f;

    const int a_row = (lane & 7) + 8 * ((lane >> 3) & 1);
    const int a_cs  = (lane >> 4) & 1;
    const int b_row = (lane & 7) + 8 * ((lane >> 4) & 1);
    const int b_cs  = (lane >> 3) & 1;
    const int a_sw = (a_row >> 1) & 3, b_sw = (b_row >> 1) & 3;
    uint32_t a_off[2], b_off[2];
    #pragma unroll
    for (int ks2 = 0; ks2 < 2; ks2++) {
        a_off[ks2] = (uint32_t)(a_row * ROW_B + (((ks2 << 1) | a_cs) ^ a_sw) * 16);
        b_off[ks2] = (uint32_t)(b_row * ROW_B + (((ks2 << 1) | b_cs) ^ b_sw) * 16);
    }

    const int l_row = tid >> 1;
    const int l_cb  = (tid & 1) << 1;
    const int l_sw  = (l_row >> 1) & 3;

    auto issue = [&](int c, int buf) {
        int k0 = c << 5;
        uint32_t base = su + (uint32_t)buf * STG;
        #pragma unroll
        for (int j = 0; j < 2; j++) {
            int ch = l_cb + j;
            size_t g = (size_t)l_row * DIMC + k0 + ch * 8;
            uint32_t so = (uint32_t)(l_row * ROW_B + (ch ^ l_sw) * 16);
            cpasync16(base + 0 * ARR_B + so, ahi + g);
            cpasync16(base + 1 * ARR_B + so, whi + g);
        }
        asm volatile("cp.async.commit_group;");
    };

    issue(0, 0);
    issue(1, 1);
    for (int c = 0; c < 32; c++) {
        if (c < 31) { asm volatile("cp.async.wait_group 1;"); }
        else        { asm volatile("cp.async.wait_group 0;"); }
        __syncthreads();
        if (c + 2 < 32) issue(c + 2, (c + 2) % 3);

        uint32_t sb = su + (uint32_t)(c % 3) * STG;

        #pragma unroll
        for (int ks2 = 0; ks2 < 2; ks2++) {
            uint32_t ah[4][4], bh[2][4];
            #pragma unroll
            for (int mt = 0; mt < 4; mt++) {
                uint32_t ab = sb + (uint32_t)((wm * 64 + mt * 16) * ROW_B) + a_off[ks2];
                ldsm4(ah[mt], ab);
            }
            #pragma unroll
            for (int p = 0; p < 2; p++) {
                uint32_t bb = sb + 1 * ARR_B
                            + (uint32_t)((wn * 32 + p * 16) * ROW_B) + b_off[ks2];
                ldsm4(bh[p], bb);
            }
            #pragma unroll
            for (int mt = 0; mt < 4; mt++)
                #pragma unroll
                for (int nt = 0; nt < 4; nt++) {
                    int p = nt >> 1, ix = (nt & 1) * 2;
                    mma16816(acc[mt][nt], ah[mt], bh[p][ix], bh[p][ix + 1]);
                }
        }
    }

    const int quad = lane >> 2, tc = lane & 3;
    #pragma unroll
    for (int mt = 0; mt < 4; mt++) {
        #pragma unroll
        for (int nt = 0; nt < 4; nt++) {
            #pragma unroll
            for (int half = 0; half < 2; half++) {
                int m = m0 + wm * 64 + mt * 16 + quad + half * 8;
                int n = n0 + wn * 32 + nt * 8 + tc * 2;
                float v0 = acc[mt][nt][half * 2]     + bias[n];
                float v1 = acc[mt][nt][half * 2 + 1] + bias[n + 1];
                if (MODE == 0) {
                    int b = m >> 11, t = m & (SEQ - 1);
                    int h = n >> 6, d = n & 63;
                    if (z == 2) {
                        size_t vb = ((size_t)(b * NH + h) * HD + d) * SEQ + t;
                        g_vthi[vb]       = __float2half_rn(v0);
                        g_vthi[vb + SEQ] = __float2half_rn(v1);
                    } else {
                        float2 cs = g_rope[t * 32 + (d >> 1)];
                        float oe = v0 * cs.x - v1 * cs.y;
                        float oo = v0 * cs.y + v1 * cs.x;
                        size_t base = ((size_t)(b * NH + h) * SEQ + t) * HD + d;
                        if (z == 0) *(uint32_t*)(g_qhi + base) = packh(oe, oo);
                        else        *(uint32_t*)(g_khi + base) = packh(oe, oo);
                    }
                } else {
                    size_t base = (size_t)m * DIMC + n;
                    outp[base]     = v0;
                    outp[base + 1] = v1;
                }
            }
        }
    }
}

// ---------------- attention: single-fp16 Q/K/V/P (unchanged, proven R16) ----------------
#define ASV 36
#define AARR (64*ASV)
#define ASTG (2*AARR)
#define ATT_SMEM_BYTES (3*ASTG*4)   // 55296

__global__ __launch_bounds__(256, 2) void attn_kernel()
{
    extern __shared__ uint32_t smu[];
    const uint32_t su = smem_u32(smu);

    const int tid  = threadIdx.x;
    const int lane = tid & 31;
    const int wid  = tid >> 5;
    const int bh   = blockIdx.y;
    const int m0   = ((int)gridDim.x - 1 - (int)blockIdx.x) * 128;

    const size_t bhb = (size_t)bh * SEQ * HD;
    const __half* Khi = g_khi + bhb;
    const __half* Vthi = g_vthi + bhb;

    const uint32_t a_loff = (uint32_t)(((lane & 7) + 8 * ((lane >> 3) & 1)) * ASV * 4
                                       + ((lane >> 4) & 1) * 16);
    const uint32_t b_loff = (uint32_t)(((lane & 7) + 8 * ((lane >> 4) & 1)) * ASV * 4
                                       + ((lane >> 3) & 1) * 16);

    {
        const __half* Qhi = g_qhi + bhb + (size_t)m0 * HD;
        #pragma unroll
        for (int j = 0; j < 4; j++) {
            int idx = tid + j * 256;
            int row = idx >> 3, seg = idx & 7;
            size_t g = (size_t)row * HD + seg * 8;
            *(uint4*)(smu + row * ASV + seg * 4) = *(const uint4*)(Qhi + g);
        }
    }
    __syncthreads();
    uint32_t qh[4][4];
    #pragma unroll
    for (int ks = 0; ks < 4; ks++) {
        uint32_t ab = su + (uint32_t)(wid * 16 * ASV * 4) + ks * 32 + a_loff;
        ldsm4(qh[ks], ab);
    }
    __syncthreads();

    float oacc[8][4];
    #pragma unroll
    for (int nt = 0; nt < 8; nt++)
        #pragma unroll
        for (int e = 0; e < 4; e++) oacc[nt][e] = 0.f;
    float lr[2] = {0.f, 0.f};

    const int qr = lane >> 2, qc = lane & 3;
    const int rowbase = m0 + wid * 16;
    const int ntiles = m0 / 64 + 2;

    const int l_row = tid >> 2, l_seg = tid & 3;

    auto issue = [&](int tix, int buf) {
        int s0 = tix * 64;
        uint32_t base = su + (uint32_t)buf * ASTG * 4;
        #pragma unroll
        for (int ss = 0; ss < 2; ss++) {
            int seg = l_seg + ss * 4;
            uint32_t so = (uint32_t)(l_row * ASV + seg * 4) * 4;
            size_t gk = (size_t)(s0 + l_row) * HD + seg * 8;
            size_t gv = (size_t)l_row * SEQ + s0 + seg * 8;
            cpasync16(base + 0 * AARR * 4 + so, Khi + gk);
            cpasync16(base + 1 * AARR * 4 + so, Vthi + gv);
        }
        asm volatile("cp.async.commit_group;");
    };

    issue(0, 0);
    issue(1, 1);
    for (int tix = 0; tix < ntiles; tix++) {
        int s0 = tix * 64;
        if (tix + 1 < ntiles) { asm volatile("cp.async.wait_group 1;"); }
        else                  { asm volatile("cp.async.wait_group 0;"); }
        __syncthreads();
        if (tix + 2 < ntiles) issue(tix + 2, (tix + 2) % 3);

        if (s0 <= rowbase + 15) {
            uint32_t kvB = su + (uint32_t)(tix % 3) * ASTG * 4;

            float sacc[8][4];
            #pragma unroll
            for (int nt = 0; nt < 8; nt++)
                #pragma unroll
                for (int e = 0; e < 4; e++) sacc[nt][e] = 0.f;

            #pragma unroll
            for (int ks = 0; ks < 4; ks++) {
                #pragma unroll
                for (int p = 0; p < 4; p++) {
                    uint32_t bb = kvB + (uint32_t)(p * 16 * ASV * 4) + ks * 32 + b_loff;
                    uint32_t kf[4];
                    ldsm4(kf, bb);
                    mma16816(sacc[2*p],   qh[ks], kf[0], kf[1]);
                    mma16816(sacc[2*p+1], qh[ks], kf[2], kf[3]);
                }
            }

            if (s0 + 63 > rowbase) {
                int rA = rowbase + qr, rB = rA + 8;
                #pragma unroll
                for (int nt = 0; nt < 8; nt++) {
                    int c0 = s0 + nt * 8 + qc * 2;
                    if (c0 > rA)     sacc[nt][0] = -1e30f;
                    if (c0 + 1 > rA) sacc[nt][1] = -1e30f;
                    if (c0 > rB)     sacc[nt][2] = -1e30f;
                    if (c0 + 1 > rB) sacc[nt][3] = -1e30f;
                }
            }

            const float C1 = 0.125f * 1.44269504f;
            #pragma unroll
            for (int nt = 0; nt < 8; nt++) {
                float p0 = fexp2(sacc[nt][0] * C1);
                float p1 = fexp2(sacc[nt][1] * C1);
                float p2 = fexp2(sacc[nt][2] * C1);
                float p3 = fexp2(sacc[nt][3] * C1);
                sacc[nt][0] = p0; sacc[nt][1] = p1;
                sacc[nt][2] = p2; sacc[nt][3] = p3;
                lr[0] += p0 + p1;
                lr[1] += p2 + p3;
            }

            uint32_t ph[4][4];
            #pragma unroll
            for (int kk = 0; kk < 4; kk++) {
                ph[kk][0] = packh(sacc[2*kk][0],   sacc[2*kk][1]);
                ph[kk][1] = packh(sacc[2*kk][2],   sacc[2*kk][3]);
                ph[kk][2] = packh(sacc[2*kk+1][0], sacc[2*kk+1][1]);
                ph[kk][3] = packh(sacc[2*kk+1][2], sacc[2*kk+1][3]);
            }

            uint32_t vbB = kvB + AARR * 4;
            #pragma unroll
            for (int kk = 0; kk < 4; kk++) {
                #pragma unroll
                for (int p = 0; p < 4; p++) {
                    uint32_t vb = vbB + (uint32_t)(p * 16 * ASV * 4) + kk * 32 + b_loff;
                    uint32_t vf[4];
                    ldsm4(vf, vb);
                    mma16816(oacc[2*p],   ph[kk], vf[0], vf[1]);
                    mma16816(oacc[2*p+1], ph[kk], vf[2], vf[3]);
                }
            }
        }
    }

    lr[0] += __shfl_xor_sync(0xffffffffu, lr[0], 1);
    lr[0] += __shfl_xor_sync(0xffffffffu, lr[0], 2);
    lr[1] += __shfl_xor_sync(0xffffffffu, lr[1], 1);
    lr[1] += __shfl_xor_sync(0xffffffffu, lr[1], 2);

    float ivA = 1.0f / lr[0], ivB = 1.0f / lr[1];
    int b = bh >> 4, h = bh & 15;
    int rA = rowbase + qr, rB = rA + 8;
    #pragma unroll
    for (int nt = 0; nt < 8; nt++) {
        int d = nt * 8 + qc * 2;
        size_t iA = ((size_t)(b * SEQ + rA)) * DIMC + h * HD + d;
        size_t iB = ((size_t)(b * SEQ + rB)) * DIMC + h * HD + d;
        *(uint32_t*)(g_ahi + iA) = packh(oacc[nt][0] * ivA, oacc[nt][1] * ivA);
        *(uint32_t*)(g_ahi + iB) = packh(oacc[nt][2] * ivB, oacc[nt][3] * ivB);
    }
}

// ---------------- launch ----------------
extern "C" void kernel_launch(void* const* d_in, const int* in_sizes, int n_in,
                              void* d_out, int out_size)
{
    const float* query = (const float*)d_in[0];
    const float* key   = (const float*)d_in[1];
    const float* value = (const float*)d_in[2];
    const float* Wq = (const float*)d_in[3];
    const float* bq = (const float*)d_in[4];
    const float* Wk = (const float*)d_in[5];
    const float* bk = (const float*)d_in[6];
    const float* Wv = (const float*)d_in[7];
    const float* bv = (const float*)d_in[8];
    const float* Wo = (const float*)d_in[9];
    const float* bo = (const float*)d_in[10];
    float* out = (float*)d_out;

    cudaFuncSetAttribute(pgemm_kernel<0>, cudaFuncAttributeMaxDynamicSharedMemorySize, GSMEM_BYTES);
    cudaFuncSetAttribute(pgemm_kernel<1>, cudaFuncAttributeMaxDynamicSharedMemorySize, GSMEM_BYTES);
    cudaFuncSetAttribute(attn_kernel, cudaFuncAttributeMaxDynamicSharedMemorySize, ATT_SMEM_BYTES);

    prep_kernel<<<PREP_BLOCKS, 256>>>((const float4*)query, (const float4*)key,
                                      (const float4*)value, Wq, Wk, Wv, Wo);

    pgemm_kernel<0><<<dim3(8, 64, 3), 256, GSMEM_BYTES>>>(bq, bk, bv, nullptr);

    attn_kernel<<<dim3(SEQ / 128, BATCH * NH), 256, ATT_SMEM_BYTES>>>();

    pgemm_kernel<1><<<dim3(8, 64, 1), 256, GSMEM_BYTES>>>(bo, nullptr, nullptr, out);
}